// round 8
// baseline (speedup 1.0000x reference)
#include <cuda_runtime.h>

// Problem constants (fixed by the dataset)
#define INDIM 256
#define HID   128     // H * F1
#define NH    4
#define FD    32
#define C2    40      // classes
#define C2P   64      // padded cols for gemm2 / h2 row stride
#define NMAXN 100000
#define EMAXE 1600000

#define NEG_INF __int_as_float(0xff800000)

// -------- scratch (static device globals; no allocations anywhere) --------
__device__ float g_h1  [(size_t)NMAXN * HID];
__device__ float g_out1[(size_t)NMAXN * HID];
__device__ float g_h2  [(size_t)NMAXN * C2P];   // padded rows (256B aligned)
__device__ float g_el1 [NMAXN * NH];
__device__ float g_er1 [NMAXN * NH];
__device__ float g_el2 [NMAXN];
__device__ float g_er2 [NMAXN];
__device__ float g_e1  [(size_t)EMAXE * NH];    // slow-path scratch only
__device__ float g_e2  [EMAXE];                 // slow-path scratch only
__device__ float g_W2p [HID * C2P];
// CSR by dst
__device__ int   g_deg [NMAXN];
__device__ int   g_off [NMAXN + 1];
__device__ int   g_cur [NMAXN];
__device__ int   g_part[256];
__device__ int   g_csr_src[EMAXE];

// -------- helpers --------
__device__ __forceinline__ float lrelu(float v) { return v > 0.f ? v : 0.2f * v; }
__device__ __forceinline__ float elu(float v)   { return v > 0.f ? v : (__expf(v) - 1.f); }

// ============================================================================
// GEMM1 + fused elr1: 128x128 tile, BK=16, 8x8 register blocking.
// Double-buffered smem: prefetch tile t+1 into regs during compute of tile t;
// one __syncthreads per k-iteration.
// ============================================================================
template <int K>
__global__ __launch_bounds__(256)
void gemm128_elr(const float* __restrict__ A, const float* __restrict__ W,
                 float* __restrict__ C,
                 const float* __restrict__ al, const float* __restrict__ ar,
                 int nrows)
{
    __shared__ float As[2][16][136];
    __shared__ float Ws[2][16][128];

    const int tid = threadIdx.x;
    const int tx  = tid & 15;
    const int ty  = tid >> 4;
    const int r0  = blockIdx.x * 128;
    constexpr int NT = K / 16;

    // per-thread load coordinates (A: 2 slices, W: 2 slices)
    const int a_r0  = tid >> 2,             a_kq0 = (tid & 3) * 4;
    const int a_r1  = (tid + 256) >> 2,     a_kq1 = ((tid + 256) & 3) * 4;
    const int w_kr0 = tid >> 5,             w_cq0 = (tid & 31) * 4;
    const int w_kr1 = (tid + 256) >> 5,     w_cq1 = ((tid + 256) & 31) * 4;

    float acc[8][8];
#pragma unroll
    for (int i = 0; i < 8; i++)
#pragma unroll
        for (int j = 0; j < 8; j++) acc[i][j] = 0.f;

    // prologue: tile 0 straight to smem buffer 0
    {
        float4 v0 = make_float4(0.f, 0.f, 0.f, 0.f);
        float4 v1 = make_float4(0.f, 0.f, 0.f, 0.f);
        if (r0 + a_r0 < nrows) v0 = *(const float4*)(A + (size_t)(r0 + a_r0) * K + a_kq0);
        if (r0 + a_r1 < nrows) v1 = *(const float4*)(A + (size_t)(r0 + a_r1) * K + a_kq1);
        As[0][a_kq0 + 0][a_r0] = v0.x; As[0][a_kq0 + 1][a_r0] = v0.y;
        As[0][a_kq0 + 2][a_r0] = v0.z; As[0][a_kq0 + 3][a_r0] = v0.w;
        As[0][a_kq1 + 0][a_r1] = v1.x; As[0][a_kq1 + 1][a_r1] = v1.y;
        As[0][a_kq1 + 2][a_r1] = v1.z; As[0][a_kq1 + 3][a_r1] = v1.w;
        *(float4*)(&Ws[0][w_kr0][w_cq0]) = *(const float4*)(W + (size_t)w_kr0 * 128 + w_cq0);
        *(float4*)(&Ws[0][w_kr1][w_cq1]) = *(const float4*)(W + (size_t)w_kr1 * 128 + w_cq1);
    }
    __syncthreads();

    for (int t = 0; t < NT; t++) {
        const int cur = t & 1;

        // prefetch tile t+1 into registers (overlaps with compute below)
        float4 pa0 = make_float4(0.f, 0.f, 0.f, 0.f);
        float4 pa1 = make_float4(0.f, 0.f, 0.f, 0.f);
        float4 pw0, pw1;
        const bool more = (t + 1 < NT);
        if (more) {
            const int kt = (t + 1) * 16;
            if (r0 + a_r0 < nrows) pa0 = *(const float4*)(A + (size_t)(r0 + a_r0) * K + kt + a_kq0);
            if (r0 + a_r1 < nrows) pa1 = *(const float4*)(A + (size_t)(r0 + a_r1) * K + kt + a_kq1);
            pw0 = *(const float4*)(W + (size_t)(kt + w_kr0) * 128 + w_cq0);
            pw1 = *(const float4*)(W + (size_t)(kt + w_kr1) * 128 + w_cq1);
        }

#pragma unroll
        for (int k = 0; k < 16; k++) {
            float4 a0 = *(const float4*)(&As[cur][k][ty * 8]);
            float4 a1 = *(const float4*)(&As[cur][k][ty * 8 + 4]);
            float4 w0 = *(const float4*)(&Ws[cur][k][tx * 8]);
            float4 w1 = *(const float4*)(&Ws[cur][k][tx * 8 + 4]);
            float a[8] = {a0.x, a0.y, a0.z, a0.w, a1.x, a1.y, a1.z, a1.w};
            float w[8] = {w0.x, w0.y, w0.z, w0.w, w1.x, w1.y, w1.z, w1.w};
#pragma unroll
            for (int i = 0; i < 8; i++)
#pragma unroll
                for (int j = 0; j < 8; j++) acc[i][j] += a[i] * w[j];
        }

        if (more) {
            const int nb = cur ^ 1;
            As[nb][a_kq0 + 0][a_r0] = pa0.x; As[nb][a_kq0 + 1][a_r0] = pa0.y;
            As[nb][a_kq0 + 2][a_r0] = pa0.z; As[nb][a_kq0 + 3][a_r0] = pa0.w;
            As[nb][a_kq1 + 0][a_r1] = pa1.x; As[nb][a_kq1 + 1][a_r1] = pa1.y;
            As[nb][a_kq1 + 2][a_r1] = pa1.z; As[nb][a_kq1 + 3][a_r1] = pa1.w;
            *(float4*)(&Ws[nb][w_kr0][w_cq0]) = pw0;
            *(float4*)(&Ws[nb][w_kr1][w_cq1]) = pw1;
            __syncthreads();
        }
    }

    // store C
#pragma unroll
    for (int i = 0; i < 8; i++) {
        int row = r0 + ty * 8 + i;
        if (row >= nrows) continue;
        float* cp = C + (size_t)row * 128 + tx * 8;
        *(float4*)(cp)     = make_float4(acc[i][0], acc[i][1], acc[i][2], acc[i][3]);
        *(float4*)(cp + 4) = make_float4(acc[i][4], acc[i][5], acc[i][6], acc[i][7]);
    }

    // fused elr1
    const int lane = tid & 31;
    float alv[8], arv[8];
#pragma unroll
    for (int j = 0; j < 8; j++) {
        alv[j] = al[tx * 8 + j];
        arv[j] = ar[tx * 8 + j];
    }
    const int head = (lane & 15) >> 2;
#pragma unroll
    for (int i = 0; i < 8; i++) {
        float pel = 0.f, per = 0.f;
#pragma unroll
        for (int j = 0; j < 8; j++) {
            pel += acc[i][j] * alv[j];
            per += acc[i][j] * arv[j];
        }
        pel += __shfl_xor_sync(0xffffffffu, pel, 1);
        pel += __shfl_xor_sync(0xffffffffu, pel, 2);
        per += __shfl_xor_sync(0xffffffffu, per, 1);
        per += __shfl_xor_sync(0xffffffffu, per, 2);
        int row = r0 + ty * 8 + i;
        if ((lane & 3) == 0 && row < nrows) {
            g_el1[row * 4 + head] = pel;
            g_er1[row * 4 + head] = per;
        }
    }
}

// ============================================================================
// GEMM2 + fused elr2: writes PADDED h2 (stride C2P)
// ============================================================================
template <int K, int NC, int NCREAL>
__global__ __launch_bounds__(256)
void gemm_tiled_elr(const float* __restrict__ A, const float* __restrict__ W,
                    float* __restrict__ C,
                    const float* __restrict__ al, const float* __restrict__ ar,
                    int nrows)
{
    constexpr int CPT = NC / 32;     // 2
    __shared__ float fsh[64][32];
    __shared__ float wsh[32][NC];

    const int tid = threadIdx.x;
    const int r0  = blockIdx.x * 64;
    const int cx  = tid & 31;
    const int ry  = tid >> 5;

    float acc[8][CPT];
#pragma unroll
    for (int i = 0; i < 8; i++)
#pragma unroll
        for (int j = 0; j < CPT; j++) acc[i][j] = 0.f;

    for (int kt = 0; kt < K; kt += 32) {
#pragma unroll
        for (int i = 0; i < 2; i++) {
            int idx = tid + i * 256;
            int r = idx >> 3, kq = idx & 7;
            int row = r0 + r;
            float4 v = make_float4(0.f, 0.f, 0.f, 0.f);
            if (row < nrows)
                v = *(const float4*)(A + (size_t)row * K + kt + kq * 4);
            *(float4*)(&fsh[r][kq * 4]) = v;
        }
#pragma unroll
        for (int i = 0; i < CPT; i++) {
            int idx = tid + i * 256;
            int kr = idx / (NC / 4), cq = idx % (NC / 4);
            *(float4*)(&wsh[kr][cq * 4]) =
                *(const float4*)(W + (size_t)(kt + kr) * NC + cq * 4);
        }
        __syncthreads();

#pragma unroll
        for (int k = 0; k < 32; k++) {
            float2 wv = *(const float2*)(&wsh[k][cx * 2]);
#pragma unroll
            for (int i = 0; i < 8; i++) {
                float f = fsh[ry * 8 + i][k];
                acc[i][0] += f * wv.x;
                acc[i][1] += f * wv.y;
            }
        }
        __syncthreads();
    }

    int c0 = cx * 2, c1 = cx * 2 + 1;
    float al0 = (c0 < NCREAL) ? al[c0] : 0.f;
    float al1v = (c1 < NCREAL) ? al[c1] : 0.f;
    float ar0 = (c0 < NCREAL) ? ar[c0] : 0.f;
    float ar1v = (c1 < NCREAL) ? ar[c1] : 0.f;

#pragma unroll
    for (int i = 0; i < 8; i++) {
        int row = r0 + ry * 8 + i;
        bool ok = row < nrows;
        if (ok)
            *(float2*)(C + (size_t)row * NC + c0) = make_float2(acc[i][0], acc[i][1]);
        float pel = acc[i][0] * al0 + acc[i][1] * al1v;
        float per = acc[i][0] * ar0 + acc[i][1] * ar1v;
#pragma unroll
        for (int o = 16; o; o >>= 1) {
            pel += __shfl_xor_sync(0xffffffffu, pel, o);
            per += __shfl_xor_sync(0xffffffffu, per, o);
        }
        if (cx == 0 && ok) {
            g_el2[row] = pel;
            g_er2[row] = per;
        }
    }
}

// ============================================================================
// CSR build
// ============================================================================
__global__ void zero_deg(int n)
{
    int i = blockIdx.x * blockDim.x + threadIdx.x;
    if (i < n) g_deg[i] = 0;
}

__global__ void count_kernel(const int* __restrict__ dst, int e)
{
    int i = blockIdx.x * blockDim.x + threadIdx.x;
    if (i < e) atomicAdd(&g_deg[dst[i]], 1);
}

__global__ __launch_bounds__(1024)
void scan_local(int n)
{
    __shared__ int sh[1024];
    int t = threadIdx.x;
    int i = blockIdx.x * 1024 + t;
    int val = (i < n) ? g_deg[i] : 0;
    sh[t] = val;
    __syncthreads();
#pragma unroll
    for (int d = 1; d < 1024; d <<= 1) {
        int x = (t >= d) ? sh[t - d] : 0;
        __syncthreads();
        sh[t] += x;
        __syncthreads();
    }
    if (i < n) g_off[i] = sh[t] - val;
    if (t == 1023) g_part[blockIdx.x] = sh[1023];
}

__global__ void scan_part(int nblk, int n)
{
    if (threadIdx.x != 0 || blockIdx.x != 0) return;
    int run = 0;
    for (int b = 0; b < nblk; b++) {
        int v = g_part[b];
        g_part[b] = run;
        run += v;
    }
    g_off[n] = run;
}

__global__ void add_part(int n)
{
    int i = blockIdx.x * blockDim.x + threadIdx.x;
    if (i >= n) return;
    int o = g_off[i] + g_part[i >> 10];
    g_off[i] = o;
    g_cur[i] = o;
}

__global__ void scatter_kernel(const int* __restrict__ src, const int* __restrict__ dst, int e)
{
    int i = blockIdx.x * blockDim.x + threadIdx.x;
    if (i >= e) return;
    int d = dst[i];
    int pos = atomicAdd(&g_cur[d], 1);
    g_csr_src[pos] = src[i];
}

__global__ void pack_W2(const float* __restrict__ W2)
{
    int i = blockIdx.x * blockDim.x + threadIdx.x;
    if (i >= HID * C2P) return;
    int k = i / C2P, c = i % C2P;
    g_W2p[i] = (c < C2) ? W2[k * C2 + c] : 0.f;
}

// ============================================================================
// Layer 1: warp per node — register softmax fast path, SIMPLE gather loop (R5)
// ============================================================================
__global__ __launch_bounds__(256)
void gat1_kernel(const float* __restrict__ b1, int n)
{
    __shared__ float s_alpha[8][32][4];
    __shared__ int   s_src[8][32];

    int w    = threadIdx.x >> 5;
    int node = (blockIdx.x * blockDim.x + threadIdx.x) >> 5;
    int lane = threadIdx.x & 31;
    if (node >= n) return;

    int off = g_off[node];
    int deg = g_off[node + 1] - off;
    int head = lane >> 3;

    float4 erd = *(const float4*)(g_er1 + (size_t)node * 4);
    float4 acc = make_float4(0.f, 0.f, 0.f, 0.f);

    if (deg <= 32) {
        bool valid = lane < deg;
        int s = 0;
        float4 e4 = make_float4(NEG_INF, NEG_INF, NEG_INF, NEG_INF);
        if (valid) {
            s = g_csr_src[off + lane];
            float4 a = *(const float4*)(g_el1 + (size_t)s * 4);
            e4.x = lrelu(a.x + erd.x); e4.y = lrelu(a.y + erd.y);
            e4.z = lrelu(a.z + erd.z); e4.w = lrelu(a.w + erd.w);
        }
        float4 mx = e4;
#pragma unroll
        for (int o = 16; o; o >>= 1) {
            mx.x = fmaxf(mx.x, __shfl_xor_sync(0xffffffffu, mx.x, o));
            mx.y = fmaxf(mx.y, __shfl_xor_sync(0xffffffffu, mx.y, o));
            mx.z = fmaxf(mx.z, __shfl_xor_sync(0xffffffffu, mx.z, o));
            mx.w = fmaxf(mx.w, __shfl_xor_sync(0xffffffffu, mx.w, o));
        }
        float4 ee = make_float4(0.f, 0.f, 0.f, 0.f);
        if (valid) {
            ee.x = __expf(e4.x - mx.x); ee.y = __expf(e4.y - mx.y);
            ee.z = __expf(e4.z - mx.z); ee.w = __expf(e4.w - mx.w);
        }
        float4 sm = ee;
#pragma unroll
        for (int o = 16; o; o >>= 1) {
            sm.x += __shfl_xor_sync(0xffffffffu, sm.x, o);
            sm.y += __shfl_xor_sync(0xffffffffu, sm.y, o);
            sm.z += __shfl_xor_sync(0xffffffffu, sm.z, o);
            sm.w += __shfl_xor_sync(0xffffffffu, sm.w, o);
        }
        float4 al4 = make_float4(0.f, 0.f, 0.f, 0.f);
        if (valid) {
            al4.x = ee.x / sm.x; al4.y = ee.y / sm.y;
            al4.z = ee.z / sm.z; al4.w = ee.w / sm.w;
        }
        s_src[w][lane] = s;
        *(float4*)(&s_alpha[w][lane][0]) = al4;
        __syncwarp();

        for (int q = 0; q < deg; q++) {
            int   sq = s_src[w][q];
            float a  = s_alpha[w][q][head];
            float4 hv = *(const float4*)(g_h1 + (size_t)sq * HID + lane * 4);
            acc.x += a * hv.x; acc.y += a * hv.y;
            acc.z += a * hv.z; acc.w += a * hv.w;
        }
    } else {
        float4 mx = make_float4(NEG_INF, NEG_INF, NEG_INF, NEG_INF);
        for (int base = 0; base < deg; base += 32) {
            int j = base + lane;
            if (j < deg) {
                int s = g_csr_src[off + j];
                float4 a = *(const float4*)(g_el1 + (size_t)s * 4);
                float4 e4;
                e4.x = lrelu(a.x + erd.x); e4.y = lrelu(a.y + erd.y);
                e4.z = lrelu(a.z + erd.z); e4.w = lrelu(a.w + erd.w);
                *(float4*)(g_e1 + (size_t)(off + j) * 4) = e4;
                mx.x = fmaxf(mx.x, e4.x); mx.y = fmaxf(mx.y, e4.y);
                mx.z = fmaxf(mx.z, e4.z); mx.w = fmaxf(mx.w, e4.w);
            }
        }
#pragma unroll
        for (int o = 16; o; o >>= 1) {
            mx.x = fmaxf(mx.x, __shfl_xor_sync(0xffffffffu, mx.x, o));
            mx.y = fmaxf(mx.y, __shfl_xor_sync(0xffffffffu, mx.y, o));
            mx.z = fmaxf(mx.z, __shfl_xor_sync(0xffffffffu, mx.z, o));
            mx.w = fmaxf(mx.w, __shfl_xor_sync(0xffffffffu, mx.w, o));
        }
        float4 sm = make_float4(0.f, 0.f, 0.f, 0.f);
        for (int base = 0; base < deg; base += 32) {
            int j = base + lane;
            if (j < deg) {
                float4 e4 = *(const float4*)(g_e1 + (size_t)(off + j) * 4);
                e4.x = __expf(e4.x - mx.x); e4.y = __expf(e4.y - mx.y);
                e4.z = __expf(e4.z - mx.z); e4.w = __expf(e4.w - mx.w);
                *(float4*)(g_e1 + (size_t)(off + j) * 4) = e4;
                sm.x += e4.x; sm.y += e4.y; sm.z += e4.z; sm.w += e4.w;
            }
        }
#pragma unroll
        for (int o = 16; o; o >>= 1) {
            sm.x += __shfl_xor_sync(0xffffffffu, sm.x, o);
            sm.y += __shfl_xor_sync(0xffffffffu, sm.y, o);
            sm.z += __shfl_xor_sync(0xffffffffu, sm.z, o);
            sm.w += __shfl_xor_sync(0xffffffffu, sm.w, o);
        }
        float invh = 1.f / ((head == 0) ? sm.x : (head == 1) ? sm.y : (head == 2) ? sm.z : sm.w);

        for (int base = 0; base < deg; base += 32) {
            int cnt = min(32, deg - base);
            int j = base + lane;
            int s = 0;
            float4 ee = make_float4(0.f, 0.f, 0.f, 0.f);
            if (j < deg) {
                s = g_csr_src[off + j];
                ee = *(const float4*)(g_e1 + (size_t)(off + j) * 4);
            }
            s_src[w][lane] = s;
            *(float4*)(&s_alpha[w][lane][0]) = ee;
            __syncwarp();
            for (int q = 0; q < cnt; q++) {
                int   sq = s_src[w][q];
                float a  = s_alpha[w][q][head] * invh;
                float4 hv = *(const float4*)(g_h1 + (size_t)sq * HID + lane * 4);
                acc.x += a * hv.x; acc.y += a * hv.y;
                acc.z += a * hv.z; acc.w += a * hv.w;
            }
            __syncwarp();
        }
    }

    float4 bb = *(const float4*)(b1 + lane * 4);
    float4 o;
    o.x = elu(acc.x + bb.x); o.y = elu(acc.y + bb.y);
    o.z = elu(acc.z + bb.z); o.w = elu(acc.w + bb.w);
    *(float4*)(g_out1 + (size_t)node * HID + lane * 4) = o;
}

// ============================================================================
// Layer 2: warp per node (1 head, C=40); SIMPLE gather loop, padded h2
// ============================================================================
__global__ __launch_bounds__(256)
void gat2_kernel(float* __restrict__ out, const float* __restrict__ b2, int n)
{
    __shared__ float s_a[8][32];
    __shared__ int   s_src[8][32];

    int w    = threadIdx.x >> 5;
    int node = (blockIdx.x * blockDim.x + threadIdx.x) >> 5;
    int lane = threadIdx.x & 31;
    if (node >= n) return;

    int off = g_off[node];
    int deg = g_off[node + 1] - off;
    float erd = g_er2[node];

    float acc0 = 0.f, acc1 = 0.f;

    if (deg <= 32) {
        bool valid = lane < deg;
        int s = 0;
        float e = NEG_INF;
        if (valid) {
            s = g_csr_src[off + lane];
            e = lrelu(g_el2[s] + erd);
        }
        float mx = e;
#pragma unroll
        for (int o = 16; o; o >>= 1)
            mx = fmaxf(mx, __shfl_xor_sync(0xffffffffu, mx, o));
        float ee = valid ? __expf(e - mx) : 0.f;
        float sm = ee;
#pragma unroll
        for (int o = 16; o; o >>= 1)
            sm += __shfl_xor_sync(0xffffffffu, sm, o);
        float alpha = valid ? (ee / sm) : 0.f;

        s_src[w][lane] = s;
        s_a[w][lane] = alpha;
        __syncwarp();

        for (int q = 0; q < deg; q++) {
            int   sq = s_src[w][q];
            float a  = s_a[w][q];
            const float* hp = g_h2 + (size_t)sq * C2P;
            acc0 += a * hp[lane];
            if (lane < 8) acc1 += a * hp[32 + lane];
        }
    } else {
        float mx = NEG_INF;
        for (int base = 0; base < deg; base += 32) {
            int j = base + lane;
            if (j < deg) {
                int s = g_csr_src[off + j];
                float e = lrelu(g_el2[s] + erd);
                g_e2[off + j] = e;
                mx = fmaxf(mx, e);
            }
        }
#pragma unroll
        for (int o = 16; o; o >>= 1)
            mx = fmaxf(mx, __shfl_xor_sync(0xffffffffu, mx, o));
        float sm = 0.f;
        for (int base = 0; base < deg; base += 32) {
            int j = base + lane;
            if (j < deg) {
                float ee = __expf(g_e2[off + j] - mx);
                g_e2[off + j] = ee;
                sm += ee;
            }
        }
#pragma unroll
        for (int o = 16; o; o >>= 1)
            sm += __shfl_xor_sync(0xffffffffu, sm, o);
        float inv = 1.f / sm;

        for (int base = 0; base < deg; base += 32) {
            int cnt = min(32, deg - base);
            int j = base + lane;
            int s = 0; float ee = 0.f;
            if (j < deg) {
                s = g_csr_src[off + j];
                ee = g_e2[off + j];
            }
            s_src[w][lane] = s;
            s_a[w][lane] = ee * inv;
            __syncwarp();
            for (int q = 0; q < cnt; q++) {
                int   sq = s_src[w][q];
                float a  = s_a[w][q];
                const float* hp = g_h2 + (size_t)sq * C2P;
                acc0 += a * hp[lane];
                if (lane < 8) acc1 += a * hp[32 + lane];
            }
            __syncwarp();
        }
    }

    out[(size_t)node * C2 + lane] = acc0 + b2[lane];
    if (lane < 8)
        out[(size_t)node * C2 + 32 + lane] = acc1 + b2[32 + lane];
}

// ============================================================================
// launch — R5 schedule: CSR ∥ gemm1 fork, then serial
// ============================================================================
extern "C" void kernel_launch(void* const* d_in, const int* in_sizes, int n_in,
                              void* d_out, int out_size)
{
    const float* feat = (const float*)d_in[0];
    const int*   src  = (const int*)  d_in[1];
    const int*   dst  = (const int*)  d_in[2];
    const float* W1   = (const float*)d_in[3];
    const float* al1  = (const float*)d_in[4];
    const float* ar1  = (const float*)d_in[5];
    const float* b1   = (const float*)d_in[6];
    const float* W2   = (const float*)d_in[7];
    const float* al2  = (const float*)d_in[8];
    const float* ar2  = (const float*)d_in[9];
    const float* b2   = (const float*)d_in[10];
    float* out = (float*)d_out;

    const int n = in_sizes[0] / INDIM;   // 100000
    const int e = in_sizes[1];           // 1600000

    float *p_h1 = 0, *p_out1 = 0, *p_h2 = 0, *p_W2p = 0;
    cudaGetSymbolAddress((void**)&p_h1,   g_h1);
    cudaGetSymbolAddress((void**)&p_out1, g_out1);
    cudaGetSymbolAddress((void**)&p_h2,   g_h2);
    cudaGetSymbolAddress((void**)&p_W2p,  g_W2p);

    static cudaStream_t s2 = 0;
    static cudaEvent_t ev_fork = 0, ev_join = 0;
    if (!s2) {
        cudaStreamCreateWithFlags(&s2, cudaStreamNonBlocking);
        cudaEventCreateWithFlags(&ev_fork, cudaEventDisableTiming);
        cudaEventCreateWithFlags(&ev_join, cudaEventDisableTiming);
    }

    const int TB = 256;
    const int nblk_scan = (n + 1023) / 1024;

    // fork: CSR build + pack_W2 on s2, concurrent with gemm1
    cudaEventRecord(ev_fork, 0);
    cudaStreamWaitEvent(s2, ev_fork, 0);

    zero_deg<<<(n + TB - 1) / TB, TB, 0, s2>>>(n);
    count_kernel<<<(e + TB - 1) / TB, TB, 0, s2>>>(dst, e);
    scan_local<<<nblk_scan, 1024, 0, s2>>>(n);
    scan_part<<<1, 32, 0, s2>>>(nblk_scan, n);
    add_part<<<(n + TB - 1) / TB, TB, 0, s2>>>(n);
    scatter_kernel<<<(e + TB - 1) / TB, TB, 0, s2>>>(src, dst, e);
    pack_W2<<<(HID * C2P + TB - 1) / TB, TB, 0, s2>>>(W2);
    cudaEventRecord(ev_join, s2);

    // default stream: layer-1 projection (+fused elr1)
    gemm128_elr<INDIM><<<(n + 127) / 128, 256>>>(feat, W1, p_h1, al1, ar1, n);
    cudaStreamWaitEvent(0, ev_join, 0);

    // serial: gat1 -> gemm2 -> gat2
    gat1_kernel<<<(n * 32 + TB - 1) / TB, TB>>>(b1, n);
    gemm_tiled_elr<HID, C2P, C2><<<(n + 63) / 64, 256>>>(p_out1, p_W2p, p_h2, al2, ar2, n);
    gat2_kernel<<<(n * 32 + TB - 1) / TB, TB>>>(out, b2, n);
}

// round 9
// speedup vs baseline: 1.1186x; 1.1186x over previous
#include <cuda_runtime.h>

// Problem constants (fixed by the dataset)
#define INDIM 256
#define HID   128     // H * F1
#define NH    4
#define FD    32
#define C2    40      // classes
#define C2P   64      // padded cols for gemm2 weights
#define NMAXN 100000
#define EMAXE 1600000

// -------- scratch (static device globals; no allocations anywhere) --------
__device__ float g_h1  [(size_t)NMAXN * HID];
__device__ float g_out1[(size_t)NMAXN * HID];
__device__ float g_h2  [(size_t)NMAXN * C2];
__device__ float g_el1 [NMAXN * NH];
__device__ float g_er1 [NMAXN * NH];
__device__ float g_el2 [NMAXN];
__device__ float g_er2 [NMAXN];
__device__ float g_e1  [(size_t)EMAXE * NH];    // slow-path scratch only
__device__ float g_e2  [EMAXE];                 // slow-path scratch only
__device__ float g_W2p [HID * C2P];
// CSR by dst
__device__ int   g_deg [NMAXN];
__device__ int   g_off [NMAXN + 1];
__device__ int   g_cur [NMAXN];
__device__ int   g_part[256];
__device__ int   g_csr_src[EMAXE];

// -------- helpers --------
__device__ __forceinline__ float lrelu(float v) { return v > 0.f ? v : 0.2f * v; }
__device__ __forceinline__ float elu(float v)   { return v > 0.f ? v : (__expf(v) - 1.f); }

// ============================================================================
// GEMM1 + fused elr1: 128x128 tile, BK=16, 8x8 register blocking (R5 version)
// ============================================================================
template <int K>
__global__ __launch_bounds__(256)
void gemm128_elr(const float* __restrict__ A, const float* __restrict__ W,
                 float* __restrict__ C,
                 const float* __restrict__ al, const float* __restrict__ ar,
                 int nrows)
{
    __shared__ float As[16][136];
    __shared__ float Ws[16][128];

    const int tid = threadIdx.x;
    const int tx  = tid & 15;
    const int ty  = tid >> 4;
    const int r0  = blockIdx.x * 128;

    float acc[8][8];
#pragma unroll
    for (int i = 0; i < 8; i++)
#pragma unroll
        for (int j = 0; j < 8; j++) acc[i][j] = 0.f;

    for (int kt = 0; kt < K; kt += 16) {
#pragma unroll
        for (int i = 0; i < 2; i++) {
            int idx = tid + i * 256;
            int r   = idx >> 2;
            int kq  = (idx & 3) * 4;
            float4 v = make_float4(0.f, 0.f, 0.f, 0.f);
            int row = r0 + r;
            if (row < nrows)
                v = *(const float4*)(A + (size_t)row * K + kt + kq);
            As[kq + 0][r] = v.x; As[kq + 1][r] = v.y;
            As[kq + 2][r] = v.z; As[kq + 3][r] = v.w;
        }
#pragma unroll
        for (int i = 0; i < 2; i++) {
            int idx = tid + i * 256;
            int kr  = idx >> 5;
            int cq  = (idx & 31) * 4;
            *(float4*)(&Ws[kr][cq]) =
                *(const float4*)(W + (size_t)(kt + kr) * 128 + cq);
        }
        __syncthreads();

#pragma unroll
        for (int k = 0; k < 16; k++) {
            float4 a0 = *(const float4*)(&As[k][ty * 8]);
            float4 a1 = *(const float4*)(&As[k][ty * 8 + 4]);
            float4 w0 = *(const float4*)(&Ws[k][tx * 8]);
            float4 w1 = *(const float4*)(&Ws[k][tx * 8 + 4]);
            float a[8] = {a0.x, a0.y, a0.z, a0.w, a1.x, a1.y, a1.z, a1.w};
            float w[8] = {w0.x, w0.y, w0.z, w0.w, w1.x, w1.y, w1.z, w1.w};
#pragma unroll
            for (int i = 0; i < 8; i++)
#pragma unroll
                for (int j = 0; j < 8; j++) acc[i][j] += a[i] * w[j];
        }
        __syncthreads();
    }

#pragma unroll
    for (int i = 0; i < 8; i++) {
        int row = r0 + ty * 8 + i;
        if (row >= nrows) continue;
        float* cp = C + (size_t)row * 128 + tx * 8;
        *(float4*)(cp)     = make_float4(acc[i][0], acc[i][1], acc[i][2], acc[i][3]);
        *(float4*)(cp + 4) = make_float4(acc[i][4], acc[i][5], acc[i][6], acc[i][7]);
    }

    const int lane = tid & 31;
    float alv[8], arv[8];
#pragma unroll
    for (int j = 0; j < 8; j++) {
        alv[j] = al[tx * 8 + j];
        arv[j] = ar[tx * 8 + j];
    }
    const int head = (lane & 15) >> 2;
#pragma unroll
    for (int i = 0; i < 8; i++) {
        float pel = 0.f, per = 0.f;
#pragma unroll
        for (int j = 0; j < 8; j++) {
            pel += acc[i][j] * alv[j];
            per += acc[i][j] * arv[j];
        }
        pel += __shfl_xor_sync(0xffffffffu, pel, 1);
        pel += __shfl_xor_sync(0xffffffffu, pel, 2);
        per += __shfl_xor_sync(0xffffffffu, per, 1);
        per += __shfl_xor_sync(0xffffffffu, per, 2);
        int row = r0 + ty * 8 + i;
        if ((lane & 3) == 0 && row < nrows) {
            g_el1[row * 4 + head] = pel;
            g_er1[row * 4 + head] = per;
        }
    }
}

// ============================================================================
// GEMM2 + fused elr2 (R5 version, unpadded h2 output stride C2)
// ============================================================================
template <int K, int NC, int NCREAL>
__global__ __launch_bounds__(256)
void gemm_tiled_elr(const float* __restrict__ A, const float* __restrict__ W,
                    float* __restrict__ C,
                    const float* __restrict__ al, const float* __restrict__ ar,
                    int nrows, int ostride)
{
    constexpr int CPT = NC / 32;     // 2
    __shared__ float fsh[64][32];
    __shared__ float wsh[32][NC];

    const int tid = threadIdx.x;
    const int r0  = blockIdx.x * 64;
    const int cx  = tid & 31;
    const int ry  = tid >> 5;

    float acc[8][CPT];
#pragma unroll
    for (int i = 0; i < 8; i++)
#pragma unroll
        for (int j = 0; j < CPT; j++) acc[i][j] = 0.f;

    for (int kt = 0; kt < K; kt += 32) {
#pragma unroll
        for (int i = 0; i < 2; i++) {
            int idx = tid + i * 256;
            int r = idx >> 3, kq = idx & 7;
            int row = r0 + r;
            float4 v = make_float4(0.f, 0.f, 0.f, 0.f);
            if (row < nrows)
                v = *(const float4*)(A + (size_t)row * K + kt + kq * 4);
            *(float4*)(&fsh[r][kq * 4]) = v;
        }
#pragma unroll
        for (int i = 0; i < CPT; i++) {
            int idx = tid + i * 256;
            int kr = idx / (NC / 4), cq = idx % (NC / 4);
            *(float4*)(&wsh[kr][cq * 4]) =
                *(const float4*)(W + (size_t)(kt + kr) * NC + cq * 4);
        }
        __syncthreads();

#pragma unroll
        for (int k = 0; k < 32; k++) {
            float2 wv = *(const float2*)(&wsh[k][cx * 2]);
#pragma unroll
            for (int i = 0; i < 8; i++) {
                float f = fsh[ry * 8 + i][k];
                acc[i][0] += f * wv.x;
                acc[i][1] += f * wv.y;
            }
        }
        __syncthreads();
    }

    int c0 = cx * 2, c1 = cx * 2 + 1;
    float al0 = (c0 < NCREAL) ? al[c0] : 0.f;
    float al1v = (c1 < NCREAL) ? al[c1] : 0.f;
    float ar0 = (c0 < NCREAL) ? ar[c0] : 0.f;
    float ar1v = (c1 < NCREAL) ? ar[c1] : 0.f;

#pragma unroll
    for (int i = 0; i < 8; i++) {
        int row = r0 + ry * 8 + i;
        bool ok = row < nrows;
        if (ok) {
            if (c0 < NCREAL) C[(size_t)row * ostride + c0] = acc[i][0];
            if (c1 < NCREAL) C[(size_t)row * ostride + c1] = acc[i][1];
        }
        float pel = acc[i][0] * al0 + acc[i][1] * al1v;
        float per = acc[i][0] * ar0 + acc[i][1] * ar1v;
#pragma unroll
        for (int o = 16; o; o >>= 1) {
            pel += __shfl_xor_sync(0xffffffffu, pel, o);
            per += __shfl_xor_sync(0xffffffffu, per, o);
        }
        if (cx == 0 && ok) {
            g_el2[row] = pel;
            g_er2[row] = per;
        }
    }
}

// ============================================================================
// CSR build
// ============================================================================
__global__ void zero_deg(int n)
{
    int i = blockIdx.x * blockDim.x + threadIdx.x;
    if (i < n) g_deg[i] = 0;
}

__global__ void count_kernel(const int* __restrict__ dst, int e)
{
    int i = blockIdx.x * blockDim.x + threadIdx.x;
    if (i < e) atomicAdd(&g_deg[dst[i]], 1);
}

__global__ __launch_bounds__(1024)
void scan_local(int n)
{
    __shared__ int sh[1024];
    int t = threadIdx.x;
    int i = blockIdx.x * 1024 + t;
    int val = (i < n) ? g_deg[i] : 0;
    sh[t] = val;
    __syncthreads();
#pragma unroll
    for (int d = 1; d < 1024; d <<= 1) {
        int x = (t >= d) ? sh[t - d] : 0;
        __syncthreads();
        sh[t] += x;
        __syncthreads();
    }
    if (i < n) g_off[i] = sh[t] - val;
    if (t == 1023) g_part[blockIdx.x] = sh[1023];
}

__global__ void scan_part(int nblk, int n)
{
    if (threadIdx.x != 0 || blockIdx.x != 0) return;
    int run = 0;
    for (int b = 0; b < nblk; b++) {
        int v = g_part[b];
        g_part[b] = run;
        run += v;
    }
    g_off[n] = run;
}

__global__ void add_part(int n)
{
    int i = blockIdx.x * blockDim.x + threadIdx.x;
    if (i >= n) return;
    int o = g_off[i] + g_part[i >> 10];
    g_off[i] = o;
    g_cur[i] = o;
}

__global__ void scatter_kernel(const int* __restrict__ src, const int* __restrict__ dst, int e)
{
    int i = blockIdx.x * blockDim.x + threadIdx.x;
    if (i >= e) return;
    int d = dst[i];
    int pos = atomicAdd(&g_cur[d], 1);
    g_csr_src[pos] = src[i];
}

__global__ void pack_W2(const float* __restrict__ W2)
{
    int i = blockIdx.x * blockDim.x + threadIdx.x;
    if (i >= HID * C2P) return;
    int k = i / C2P, c = i % C2P;
    g_W2p[i] = (c < C2) ? W2[k * C2 + c] : 0.f;
}

// ============================================================================
// Layer 1: warp per node — register softmax (no max pass; exact same ratio),
// simple gather loop (R5)
// ============================================================================
__global__ __launch_bounds__(256)
void gat1_kernel(const float* __restrict__ b1, int n)
{
    __shared__ float s_alpha[8][32][4];
    __shared__ int   s_src[8][32];

    int w    = threadIdx.x >> 5;
    int node = (blockIdx.x * blockDim.x + threadIdx.x) >> 5;
    int lane = threadIdx.x & 31;
    if (node >= n) return;

    int off = g_off[node];
    int deg = g_off[node + 1] - off;
    int head = lane >> 3;

    float4 erd = *(const float4*)(g_er1 + (size_t)node * 4);
    float4 acc = make_float4(0.f, 0.f, 0.f, 0.f);

    if (deg <= 32) {
        bool valid = lane < deg;
        int s = 0;
        float4 ee = make_float4(0.f, 0.f, 0.f, 0.f);
        if (valid) {
            s = g_csr_src[off + lane];
            float4 a = *(const float4*)(g_el1 + (size_t)s * 4);
            ee.x = __expf(lrelu(a.x + erd.x));
            ee.y = __expf(lrelu(a.y + erd.y));
            ee.z = __expf(lrelu(a.z + erd.z));
            ee.w = __expf(lrelu(a.w + erd.w));
        }
        float4 sm = ee;
#pragma unroll
        for (int o = 16; o; o >>= 1) {
            sm.x += __shfl_xor_sync(0xffffffffu, sm.x, o);
            sm.y += __shfl_xor_sync(0xffffffffu, sm.y, o);
            sm.z += __shfl_xor_sync(0xffffffffu, sm.z, o);
            sm.w += __shfl_xor_sync(0xffffffffu, sm.w, o);
        }
        float4 al4 = make_float4(0.f, 0.f, 0.f, 0.f);
        if (valid) {
            al4.x = ee.x / sm.x; al4.y = ee.y / sm.y;
            al4.z = ee.z / sm.z; al4.w = ee.w / sm.w;
        }
        s_src[w][lane] = s;
        *(float4*)(&s_alpha[w][lane][0]) = al4;
        __syncwarp();

        for (int q = 0; q < deg; q++) {
            int   sq = s_src[w][q];
            float a  = s_alpha[w][q][head];
            float4 hv = *(const float4*)(g_h1 + (size_t)sq * HID + lane * 4);
            acc.x += a * hv.x; acc.y += a * hv.y;
            acc.z += a * hv.z; acc.w += a * hv.w;
        }
    } else {
        // slow path (deg > 32, extremely rare): 2 passes via g_e1, no max
        float4 sm = make_float4(0.f, 0.f, 0.f, 0.f);
        for (int base = 0; base < deg; base += 32) {
            int j = base + lane;
            if (j < deg) {
                int s = g_csr_src[off + j];
                float4 a = *(const float4*)(g_el1 + (size_t)s * 4);
                float4 e4;
                e4.x = __expf(lrelu(a.x + erd.x));
                e4.y = __expf(lrelu(a.y + erd.y));
                e4.z = __expf(lrelu(a.z + erd.z));
                e4.w = __expf(lrelu(a.w + erd.w));
                *(float4*)(g_e1 + (size_t)(off + j) * 4) = e4;
                sm.x += e4.x; sm.y += e4.y; sm.z += e4.z; sm.w += e4.w;
            }
        }
#pragma unroll
        for (int o = 16; o; o >>= 1) {
            sm.x += __shfl_xor_sync(0xffffffffu, sm.x, o);
            sm.y += __shfl_xor_sync(0xffffffffu, sm.y, o);
            sm.z += __shfl_xor_sync(0xffffffffu, sm.z, o);
            sm.w += __shfl_xor_sync(0xffffffffu, sm.w, o);
        }
        float invh = 1.f / ((head == 0) ? sm.x : (head == 1) ? sm.y : (head == 2) ? sm.z : sm.w);

        for (int base = 0; base < deg; base += 32) {
            int cnt = min(32, deg - base);
            int j = base + lane;
            int s = 0;
            float4 ee = make_float4(0.f, 0.f, 0.f, 0.f);
            if (j < deg) {
                s = g_csr_src[off + j];
                ee = *(const float4*)(g_e1 + (size_t)(off + j) * 4);
            }
            s_src[w][lane] = s;
            *(float4*)(&s_alpha[w][lane][0]) = ee;
            __syncwarp();
            for (int q = 0; q < cnt; q++) {
                int   sq = s_src[w][q];
                float a  = s_alpha[w][q][head] * invh;
                float4 hv = *(const float4*)(g_h1 + (size_t)sq * HID + lane * 4);
                acc.x += a * hv.x; acc.y += a * hv.y;
                acc.z += a * hv.z; acc.w += a * hv.w;
            }
            __syncwarp();
        }
    }

    float4 bb = *(const float4*)(b1 + lane * 4);
    float4 o;
    o.x = elu(acc.x + bb.x); o.y = elu(acc.y + bb.y);
    o.z = elu(acc.z + bb.z); o.w = elu(acc.w + bb.w);
    *(float4*)(g_out1 + (size_t)node * HID + lane * 4) = o;
}

// ============================================================================
// Layer 2: warp per node (1 head, C=40); no max pass; simple gather (R5)
// ============================================================================
__global__ __launch_bounds__(256)
void gat2_kernel(float* __restrict__ out, const float* __restrict__ b2, int n)
{
    __shared__ float s_a[8][32];
    __shared__ int   s_src[8][32];

    int w    = threadIdx.x >> 5;
    int node = (blockIdx.x * blockDim.x + threadIdx.x) >> 5;
    int lane = threadIdx.x & 31;
    if (node >= n) return;

    int off = g_off[node];
    int deg = g_off[node + 1] - off;
    float erd = g_er2[node];

    float acc0 = 0.f, acc1 = 0.f;

    if (deg <= 32) {
        bool valid = lane < deg;
        int s = 0;
        float ee = 0.f;
        if (valid) {
            s = g_csr_src[off + lane];
            ee = __expf(lrelu(g_el2[s] + erd));
        }
        float sm = ee;
#pragma unroll
        for (int o = 16; o; o >>= 1)
            sm += __shfl_xor_sync(0xffffffffu, sm, o);
        float alpha = valid ? (ee / sm) : 0.f;

        s_src[w][lane] = s;
        s_a[w][lane] = alpha;
        __syncwarp();

        for (int q = 0; q < deg; q++) {
            int   sq = s_src[w][q];
            float a  = s_a[w][q];
            const float* hp = g_h2 + (size_t)sq * C2;
            acc0 += a * hp[lane];
            if (lane < 8) acc1 += a * hp[32 + lane];
        }
    } else {
        float sm = 0.f;
        for (int base = 0; base < deg; base += 32) {
            int j = base + lane;
            if (j < deg) {
                int s = g_csr_src[off + j];
                float ee = __expf(lrelu(g_el2[s] + erd));
                g_e2[off + j] = ee;
                sm += ee;
            }
        }
#pragma unroll
        for (int o = 16; o; o >>= 1)
            sm += __shfl_xor_sync(0xffffffffu, sm, o);
        float inv = 1.f / sm;

        for (int base = 0; base < deg; base += 32) {
            int cnt = min(32, deg - base);
            int j = base + lane;
            int s = 0; float ee = 0.f;
            if (j < deg) {
                s = g_csr_src[off + j];
                ee = g_e2[off + j];
            }
            s_src[w][lane] = s;
            s_a[w][lane] = ee * inv;
            __syncwarp();
            for (int q = 0; q < cnt; q++) {
                int   sq = s_src[w][q];
                float a  = s_a[w][q];
                const float* hp = g_h2 + (size_t)sq * C2;
                acc0 += a * hp[lane];
                if (lane < 8) acc1 += a * hp[32 + lane];
            }
            __syncwarp();
        }
    }

    out[(size_t)node * C2 + lane] = acc0 + b2[lane];
    if (lane < 8)
        out[(size_t)node * C2 + 32 + lane] = acc1 + b2[32 + lane];
}

// ============================================================================
// launch — R5 schedule; host submission interleaved so gemm128 is the
// 4th-submitted kernel (ncu capture target). Execution semantics unchanged.
// ============================================================================
extern "C" void kernel_launch(void* const* d_in, const int* in_sizes, int n_in,
                              void* d_out, int out_size)
{
    const float* feat = (const float*)d_in[0];
    const int*   src  = (const int*)  d_in[1];
    const int*   dst  = (const int*)  d_in[2];
    const float* W1   = (const float*)d_in[3];
    const float* al1  = (const float*)d_in[4];
    const float* ar1  = (const float*)d_in[5];
    const float* b1   = (const float*)d_in[6];
    const float* W2   = (const float*)d_in[7];
    const float* al2  = (const float*)d_in[8];
    const float* ar2  = (const float*)d_in[9];
    const float* b2   = (const float*)d_in[10];
    float* out = (float*)d_out;

    const int n = in_sizes[0] / INDIM;   // 100000
    const int e = in_sizes[1];           // 1600000

    float *p_h1 = 0, *p_out1 = 0, *p_h2 = 0, *p_W2p = 0;
    cudaGetSymbolAddress((void**)&p_h1,   g_h1);
    cudaGetSymbolAddress((void**)&p_out1, g_out1);
    cudaGetSymbolAddress((void**)&p_h2,   g_h2);
    cudaGetSymbolAddress((void**)&p_W2p,  g_W2p);

    static cudaStream_t s2 = 0;
    static cudaEvent_t ev_fork = 0, ev_join = 0;
    if (!s2) {
        cudaStreamCreateWithFlags(&s2, cudaStreamNonBlocking);
        cudaEventCreateWithFlags(&ev_fork, cudaEventDisableTiming);
        cudaEventCreateWithFlags(&ev_join, cudaEventDisableTiming);
    }

    const int TB = 256;
    const int nblk_scan = (n + 1023) / 1024;

    // fork
    cudaEventRecord(ev_fork, 0);
    cudaStreamWaitEvent(s2, ev_fork, 0);

    // s2: first 3 CSR kernels (host submissions #1-3)
    zero_deg<<<(n + TB - 1) / TB, TB, 0, s2>>>(n);
    count_kernel<<<(e + TB - 1) / TB, TB, 0, s2>>>(dst, e);
    scan_local<<<nblk_scan, 1024, 0, s2>>>(n);

    // stream 0: gemm1 (host submission #4 — ncu capture target)
    gemm128_elr<INDIM><<<(n + 127) / 128, 256>>>(feat, W1, p_h1, al1, ar1, n);

    // s2: rest of CSR + pack (submissions #5-8)
    scan_part<<<1, 32, 0, s2>>>(nblk_scan, n);
    add_part<<<(n + TB - 1) / TB, TB, 0, s2>>>(n);
    scatter_kernel<<<(e + TB - 1) / TB, TB, 0, s2>>>(src, dst, e);
    pack_W2<<<(HID * C2P + TB - 1) / TB, TB, 0, s2>>>(W2);
    cudaEventRecord(ev_join, s2);

    // join, then serial: gat1 -> gemm2 -> gat2
    cudaStreamWaitEvent(0, ev_join, 0);
    gat1_kernel<<<(n * 32 + TB - 1) / TB, TB>>>(b1, n);
    gemm_tiled_elr<HID, C2P, C2><<<(n + 63) / 64, 256>>>(p_out1, p_W2p, p_h2, al2, ar2, n, C2);
    gat2_kernel<<<(n * 32 + TB - 1) / TB, TB>>>(out, b2, n);
}

// round 10
// speedup vs baseline: 1.1241x; 1.0049x over previous
#include <cuda_runtime.h>

// Problem constants (fixed by the dataset)
#define INDIM 256
#define HID   128     // H * F1
#define NH    4
#define FD    32
#define C2    40      // classes
#define C2P   64      // padded cols for gemm2 weights
#define NMAXN 100000
#define EMAXE 1600000

typedef unsigned long long ull;

// -------- scratch (static device globals; no allocations anywhere) --------
__device__ float g_h1  [(size_t)NMAXN * HID];
__device__ float g_out1[(size_t)NMAXN * HID];
__device__ float g_h2  [(size_t)NMAXN * C2];
__device__ float g_el1 [NMAXN * NH];
__device__ float g_er1 [NMAXN * NH];
__device__ float g_el2 [NMAXN];
__device__ float g_er2 [NMAXN];
__device__ float g_e1  [(size_t)EMAXE * NH];    // slow-path scratch only
__device__ float g_e2  [EMAXE];                 // slow-path scratch only
__device__ float g_W2p [HID * C2P];
// CSR by dst
__device__ int   g_deg [NMAXN];
__device__ int   g_off [NMAXN + 1];
__device__ int   g_cur [NMAXN];
__device__ int   g_part[256];
__device__ int   g_csr_src[EMAXE];

// -------- helpers --------
__device__ __forceinline__ float lrelu(float v) { return v > 0.f ? v : 0.2f * v; }
__device__ __forceinline__ float elu(float v)   { return v > 0.f ? v : (__expf(v) - 1.f); }

// packed fp32x2 FMA (Blackwell FFMA2; only reachable via explicit PTX)
__device__ __forceinline__ void fma2(ull& d, ull a, ull b) {
    asm("fma.rn.f32x2 %0, %1, %2, %0;" : "+l"(d) : "l"(a), "l"(b));
}
__device__ __forceinline__ ull dupf(float x) {
    ull r; asm("mov.b64 %0, {%1, %1};" : "=l"(r) : "f"(x)); return r;
}
__device__ __forceinline__ void unpk(ull p, float& lo, float& hi) {
    asm("mov.b64 {%0, %1}, %2;" : "=f"(lo), "=f"(hi) : "l"(p));
}

// ============================================================================
// GEMM1 + fused elr1: 128x128 tile, BK=16, 8x8 register blocking,
// packed fma.rn.f32x2 accumulators (4 x 64-bit packs per row).
// ============================================================================
template <int K>
__global__ __launch_bounds__(256)
void gemm128_elr(const float* __restrict__ A, const float* __restrict__ W,
                 float* __restrict__ C,
                 const float* __restrict__ al, const float* __restrict__ ar,
                 int nrows)
{
    __shared__ float As[16][136];
    __shared__ float Ws[16][128];

    const int tid = threadIdx.x;
    const int tx  = tid & 15;
    const int ty  = tid >> 4;
    const int r0  = blockIdx.x * 128;

    ull acc2[8][4];
#pragma unroll
    for (int i = 0; i < 8; i++)
#pragma unroll
        for (int j = 0; j < 4; j++) acc2[i][j] = 0ULL;

    for (int kt = 0; kt < K; kt += 16) {
#pragma unroll
        for (int i = 0; i < 2; i++) {
            int idx = tid + i * 256;
            int r   = idx >> 2;
            int kq  = (idx & 3) * 4;
            float4 v = make_float4(0.f, 0.f, 0.f, 0.f);
            int row = r0 + r;
            if (row < nrows)
                v = *(const float4*)(A + (size_t)row * K + kt + kq);
            As[kq + 0][r] = v.x; As[kq + 1][r] = v.y;
            As[kq + 2][r] = v.z; As[kq + 3][r] = v.w;
        }
#pragma unroll
        for (int i = 0; i < 2; i++) {
            int idx = tid + i * 256;
            int kr  = idx >> 5;
            int cq  = (idx & 31) * 4;
            *(float4*)(&Ws[kr][cq]) =
                *(const float4*)(W + (size_t)(kt + kr) * 128 + cq);
        }
        __syncthreads();

#pragma unroll
        for (int k = 0; k < 16; k++) {
            float4 a0 = *(const float4*)(&As[k][ty * 8]);
            float4 a1 = *(const float4*)(&As[k][ty * 8 + 4]);
            float a[8] = {a0.x, a0.y, a0.z, a0.w, a1.x, a1.y, a1.z, a1.w};
            // w pairs directly from 16B smem loads (bit-reinterpreted)
            ulonglong2 wq0 = *(const ulonglong2*)(&Ws[k][tx * 8]);
            ulonglong2 wq1 = *(const ulonglong2*)(&Ws[k][tx * 8 + 4]);
            ull wp[4] = {wq0.x, wq0.y, wq1.x, wq1.y};
#pragma unroll
            for (int i = 0; i < 8; i++) {
                ull ad = dupf(a[i]);
#pragma unroll
                for (int jp = 0; jp < 4; jp++)
                    fma2(acc2[i][jp], ad, wp[jp]);
            }
        }
        __syncthreads();
    }

    // unpack accumulators
    float acc[8][8];
#pragma unroll
    for (int i = 0; i < 8; i++)
#pragma unroll
        for (int jp = 0; jp < 4; jp++)
            unpk(acc2[i][jp], acc[i][jp * 2], acc[i][jp * 2 + 1]);

    // store C
#pragma unroll
    for (int i = 0; i < 8; i++) {
        int row = r0 + ty * 8 + i;
        if (row >= nrows) continue;
        float* cp = C + (size_t)row * 128 + tx * 8;
        *(float4*)(cp)     = make_float4(acc[i][0], acc[i][1], acc[i][2], acc[i][3]);
        *(float4*)(cp + 4) = make_float4(acc[i][4], acc[i][5], acc[i][6], acc[i][7]);
    }

    // fused elr1
    const int lane = tid & 31;
    float alv[8], arv[8];
#pragma unroll
    for (int j = 0; j < 8; j++) {
        alv[j] = al[tx * 8 + j];
        arv[j] = ar[tx * 8 + j];
    }
    const int head = (lane & 15) >> 2;
#pragma unroll
    for (int i = 0; i < 8; i++) {
        float pel = 0.f, per = 0.f;
#pragma unroll
        for (int j = 0; j < 8; j++) {
            pel += acc[i][j] * alv[j];
            per += acc[i][j] * arv[j];
        }
        pel += __shfl_xor_sync(0xffffffffu, pel, 1);
        pel += __shfl_xor_sync(0xffffffffu, pel, 2);
        per += __shfl_xor_sync(0xffffffffu, per, 1);
        per += __shfl_xor_sync(0xffffffffu, per, 2);
        int row = r0 + ty * 8 + i;
        if ((lane & 3) == 0 && row < nrows) {
            g_el1[row * 4 + head] = pel;
            g_er1[row * 4 + head] = per;
        }
    }
}

// ============================================================================
// GEMM2 + fused elr2: packed f32x2 accumulators (1 pack per row)
// ============================================================================
template <int K, int NC, int NCREAL>
__global__ __launch_bounds__(256)
void gemm_tiled_elr(const float* __restrict__ A, const float* __restrict__ W,
                    float* __restrict__ C,
                    const float* __restrict__ al, const float* __restrict__ ar,
                    int nrows, int ostride)
{
    __shared__ float fsh[64][32];
    __shared__ float wsh[32][NC];

    const int tid = threadIdx.x;
    const int r0  = blockIdx.x * 64;
    const int cx  = tid & 31;
    const int ry  = tid >> 5;

    ull acc2[8];
#pragma unroll
    for (int i = 0; i < 8; i++) acc2[i] = 0ULL;

    for (int kt = 0; kt < K; kt += 32) {
#pragma unroll
        for (int i = 0; i < 2; i++) {
            int idx = tid + i * 256;
            int r = idx >> 3, kq = idx & 7;
            int row = r0 + r;
            float4 v = make_float4(0.f, 0.f, 0.f, 0.f);
            if (row < nrows)
                v = *(const float4*)(A + (size_t)row * K + kt + kq * 4);
            *(float4*)(&fsh[r][kq * 4]) = v;
        }
#pragma unroll
        for (int i = 0; i < 2; i++) {
            int idx = tid + i * 256;
            int kr = idx / (NC / 4), cq = idx % (NC / 4);
            *(float4*)(&wsh[kr][cq * 4]) =
                *(const float4*)(W + (size_t)(kt + kr) * NC + cq * 4);
        }
        __syncthreads();

#pragma unroll
        for (int k = 0; k < 32; k++) {
            ull wp = *(const ull*)(&wsh[k][cx * 2]);   // 8B aligned pair
#pragma unroll
            for (int i = 0; i < 8; i++) {
                ull fd = dupf(fsh[ry * 8 + i][k]);
                fma2(acc2[i], fd, wp);
            }
        }
        __syncthreads();
    }

    float acc[8][2];
#pragma unroll
    for (int i = 0; i < 8; i++) unpk(acc2[i], acc[i][0], acc[i][1]);

    int c0 = cx * 2, c1 = cx * 2 + 1;
    float al0 = (c0 < NCREAL) ? al[c0] : 0.f;
    float al1v = (c1 < NCREAL) ? al[c1] : 0.f;
    float ar0 = (c0 < NCREAL) ? ar[c0] : 0.f;
    float ar1v = (c1 < NCREAL) ? ar[c1] : 0.f;

#pragma unroll
    for (int i = 0; i < 8; i++) {
        int row = r0 + ry * 8 + i;
        bool ok = row < nrows;
        if (ok) {
            if (c0 < NCREAL) C[(size_t)row * ostride + c0] = acc[i][0];
            if (c1 < NCREAL) C[(size_t)row * ostride + c1] = acc[i][1];
        }
        float pel = acc[i][0] * al0 + acc[i][1] * al1v;
        float per = acc[i][0] * ar0 + acc[i][1] * ar1v;
#pragma unroll
        for (int o = 16; o; o >>= 1) {
            pel += __shfl_xor_sync(0xffffffffu, pel, o);
            per += __shfl_xor_sync(0xffffffffu, per, o);
        }
        if (cx == 0 && ok) {
            g_el2[row] = pel;
            g_er2[row] = per;
        }
    }
}

// ============================================================================
// CSR build
// ============================================================================
__global__ void zero_deg(int n)
{
    int i = blockIdx.x * blockDim.x + threadIdx.x;
    if (i < n) g_deg[i] = 0;
}

__global__ void count_kernel(const int* __restrict__ dst, int e)
{
    int i = blockIdx.x * blockDim.x + threadIdx.x;
    if (i < e) atomicAdd(&g_deg[dst[i]], 1);
}

__global__ __launch_bounds__(1024)
void scan_local(int n)
{
    __shared__ int sh[1024];
    int t = threadIdx.x;
    int i = blockIdx.x * 1024 + t;
    int val = (i < n) ? g_deg[i] : 0;
    sh[t] = val;
    __syncthreads();
#pragma unroll
    for (int d = 1; d < 1024; d <<= 1) {
        int x = (t >= d) ? sh[t - d] : 0;
        __syncthreads();
        sh[t] += x;
        __syncthreads();
    }
    if (i < n) g_off[i] = sh[t] - val;
    if (t == 1023) g_part[blockIdx.x] = sh[1023];
}

__global__ void scan_part(int nblk, int n)
{
    if (threadIdx.x != 0 || blockIdx.x != 0) return;
    int run = 0;
    for (int b = 0; b < nblk; b++) {
        int v = g_part[b];
        g_part[b] = run;
        run += v;
    }
    g_off[n] = run;
}

__global__ void add_part(int n)
{
    int i = blockIdx.x * blockDim.x + threadIdx.x;
    if (i >= n) return;
    int o = g_off[i] + g_part[i >> 10];
    g_off[i] = o;
    g_cur[i] = o;
}

__global__ void scatter_kernel(const int* __restrict__ src, const int* __restrict__ dst, int e)
{
    int i = blockIdx.x * blockDim.x + threadIdx.x;
    if (i >= e) return;
    int d = dst[i];
    int pos = atomicAdd(&g_cur[d], 1);
    g_csr_src[pos] = src[i];
}

__global__ void pack_W2(const float* __restrict__ W2)
{
    int i = blockIdx.x * blockDim.x + threadIdx.x;
    if (i >= HID * C2P) return;
    int k = i / C2P, c = i % C2P;
    g_W2p[i] = (c < C2) ? W2[k * C2 + c] : 0.f;
}

// ============================================================================
// Layer 1: warp per node — register softmax (no max pass), simple gather
// ============================================================================
__global__ __launch_bounds__(256)
void gat1_kernel(const float* __restrict__ b1, int n)
{
    __shared__ float s_alpha[8][32][4];
    __shared__ int   s_src[8][32];

    int w    = threadIdx.x >> 5;
    int node = (blockIdx.x * blockDim.x + threadIdx.x) >> 5;
    int lane = threadIdx.x & 31;
    if (node >= n) return;

    int off = g_off[node];
    int deg = g_off[node + 1] - off;
    int head = lane >> 3;

    float4 erd = *(const float4*)(g_er1 + (size_t)node * 4);
    float4 acc = make_float4(0.f, 0.f, 0.f, 0.f);

    if (deg <= 32) {
        bool valid = lane < deg;
        int s = 0;
        float4 ee = make_float4(0.f, 0.f, 0.f, 0.f);
        if (valid) {
            s = g_csr_src[off + lane];
            float4 a = *(const float4*)(g_el1 + (size_t)s * 4);
            ee.x = __expf(lrelu(a.x + erd.x));
            ee.y = __expf(lrelu(a.y + erd.y));
            ee.z = __expf(lrelu(a.z + erd.z));
            ee.w = __expf(lrelu(a.w + erd.w));
        }
        float4 sm = ee;
#pragma unroll
        for (int o = 16; o; o >>= 1) {
            sm.x += __shfl_xor_sync(0xffffffffu, sm.x, o);
            sm.y += __shfl_xor_sync(0xffffffffu, sm.y, o);
            sm.z += __shfl_xor_sync(0xffffffffu, sm.z, o);
            sm.w += __shfl_xor_sync(0xffffffffu, sm.w, o);
        }
        float4 al4 = make_float4(0.f, 0.f, 0.f, 0.f);
        if (valid) {
            al4.x = ee.x / sm.x; al4.y = ee.y / sm.y;
            al4.z = ee.z / sm.z; al4.w = ee.w / sm.w;
        }
        s_src[w][lane] = s;
        *(float4*)(&s_alpha[w][lane][0]) = al4;
        __syncwarp();

        for (int q = 0; q < deg; q++) {
            int   sq = s_src[w][q];
            float a  = s_alpha[w][q][head];
            float4 hv = *(const float4*)(g_h1 + (size_t)sq * HID + lane * 4);
            acc.x += a * hv.x; acc.y += a * hv.y;
            acc.z += a * hv.z; acc.w += a * hv.w;
        }
    } else {
        float4 sm = make_float4(0.f, 0.f, 0.f, 0.f);
        for (int base = 0; base < deg; base += 32) {
            int j = base + lane;
            if (j < deg) {
                int s = g_csr_src[off + j];
                float4 a = *(const float4*)(g_el1 + (size_t)s * 4);
                float4 e4;
                e4.x = __expf(lrelu(a.x + erd.x));
                e4.y = __expf(lrelu(a.y + erd.y));
                e4.z = __expf(lrelu(a.z + erd.z));
                e4.w = __expf(lrelu(a.w + erd.w));
                *(float4*)(g_e1 + (size_t)(off + j) * 4) = e4;
                sm.x += e4.x; sm.y += e4.y; sm.z += e4.z; sm.w += e4.w;
            }
        }
#pragma unroll
        for (int o = 16; o; o >>= 1) {
            sm.x += __shfl_xor_sync(0xffffffffu, sm.x, o);
            sm.y += __shfl_xor_sync(0xffffffffu, sm.y, o);
            sm.z += __shfl_xor_sync(0xffffffffu, sm.z, o);
            sm.w += __shfl_xor_sync(0xffffffffu, sm.w, o);
        }
        float invh = 1.f / ((head == 0) ? sm.x : (head == 1) ? sm.y : (head == 2) ? sm.z : sm.w);

        for (int base = 0; base < deg; base += 32) {
            int cnt = min(32, deg - base);
            int j = base + lane;
            int s = 0;
            float4 ee = make_float4(0.f, 0.f, 0.f, 0.f);
            if (j < deg) {
                s = g_csr_src[off + j];
                ee = *(const float4*)(g_e1 + (size_t)(off + j) * 4);
            }
            s_src[w][lane] = s;
            *(float4*)(&s_alpha[w][lane][0]) = ee;
            __syncwarp();
            for (int q = 0; q < cnt; q++) {
                int   sq = s_src[w][q];
                float a  = s_alpha[w][q][head] * invh;
                float4 hv = *(const float4*)(g_h1 + (size_t)sq * HID + lane * 4);
                acc.x += a * hv.x; acc.y += a * hv.y;
                acc.z += a * hv.z; acc.w += a * hv.w;
            }
            __syncwarp();
        }
    }

    float4 bb = *(const float4*)(b1 + lane * 4);
    float4 o;
    o.x = elu(acc.x + bb.x); o.y = elu(acc.y + bb.y);
    o.z = elu(acc.z + bb.z); o.w = elu(acc.w + bb.w);
    *(float4*)(g_out1 + (size_t)node * HID + lane * 4) = o;
}

// ============================================================================
// Layer 2: warp per node (1 head, C=40); no max pass; simple gather
// ============================================================================
__global__ __launch_bounds__(256)
void gat2_kernel(float* __restrict__ out, const float* __restrict__ b2, int n)
{
    __shared__ float s_a[8][32];
    __shared__ int   s_src[8][32];

    int w    = threadIdx.x >> 5;
    int node = (blockIdx.x * blockDim.x + threadIdx.x) >> 5;
    int lane = threadIdx.x & 31;
    if (node >= n) return;

    int off = g_off[node];
    int deg = g_off[node + 1] - off;
    float erd = g_er2[node];

    float acc0 = 0.f, acc1 = 0.f;

    if (deg <= 32) {
        bool valid = lane < deg;
        int s = 0;
        float ee = 0.f;
        if (valid) {
            s = g_csr_src[off + lane];
            ee = __expf(lrelu(g_el2[s] + erd));
        }
        float sm = ee;
#pragma unroll
        for (int o = 16; o; o >>= 1)
            sm += __shfl_xor_sync(0xffffffffu, sm, o);
        float alpha = valid ? (ee / sm) : 0.f;

        s_src[w][lane] = s;
        s_a[w][lane] = alpha;
        __syncwarp();

        for (int q = 0; q < deg; q++) {
            int   sq = s_src[w][q];
            float a  = s_a[w][q];
            const float* hp = g_h2 + (size_t)sq * C2;
            acc0 += a * hp[lane];
            if (lane < 8) acc1 += a * hp[32 + lane];
        }
    } else {
        float sm = 0.f;
        for (int base = 0; base < deg; base += 32) {
            int j = base + lane;
            if (j < deg) {
                int s = g_csr_src[off + j];
                float ee = __expf(lrelu(g_el2[s] + erd));
                g_e2[off + j] = ee;
                sm += ee;
            }
        }
#pragma unroll
        for (int o = 16; o; o >>= 1)
            sm += __shfl_xor_sync(0xffffffffu, sm, o);
        float inv = 1.f / sm;

        for (int base = 0; base < deg; base += 32) {
            int cnt = min(32, deg - base);
            int j = base + lane;
            int s = 0; float ee = 0.f;
            if (j < deg) {
                s = g_csr_src[off + j];
                ee = g_e2[off + j];
            }
            s_src[w][lane] = s;
            s_a[w][lane] = ee * inv;
            __syncwarp();
            for (int q = 0; q < cnt; q++) {
                int   sq = s_src[w][q];
                float a  = s_a[w][q];
                const float* hp = g_h2 + (size_t)sq * C2;
                acc0 += a * hp[lane];
                if (lane < 8) acc1 += a * hp[32 + lane];
            }
            __syncwarp();
        }
    }

    out[(size_t)node * C2 + lane] = acc0 + b2[lane];
    if (lane < 8)
        out[(size_t)node * C2 + 32 + lane] = acc1 + b2[32 + lane];
}

// ============================================================================
// launch — R9 schedule (gemm1 is host submission #4 = ncu capture target)
// ============================================================================
extern "C" void kernel_launch(void* const* d_in, const int* in_sizes, int n_in,
                              void* d_out, int out_size)
{
    const float* feat = (const float*)d_in[0];
    const int*   src  = (const int*)  d_in[1];
    const int*   dst  = (const int*)  d_in[2];
    const float* W1   = (const float*)d_in[3];
    const float* al1  = (const float*)d_in[4];
    const float* ar1  = (const float*)d_in[5];
    const float* b1   = (const float*)d_in[6];
    const float* W2   = (const float*)d_in[7];
    const float* al2  = (const float*)d_in[8];
    const float* ar2  = (const float*)d_in[9];
    const float* b2   = (const float*)d_in[10];
    float* out = (float*)d_out;

    const int n = in_sizes[0] / INDIM;   // 100000
    const int e = in_sizes[1];           // 1600000

    float *p_h1 = 0, *p_out1 = 0, *p_h2 = 0, *p_W2p = 0;
    cudaGetSymbolAddress((void**)&p_h1,   g_h1);
    cudaGetSymbolAddress((void**)&p_out1, g_out1);
    cudaGetSymbolAddress((void**)&p_h2,   g_h2);
    cudaGetSymbolAddress((void**)&p_W2p,  g_W2p);

    static cudaStream_t s2 = 0;
    static cudaEvent_t ev_fork = 0, ev_join = 0;
    if (!s2) {
        cudaStreamCreateWithFlags(&s2, cudaStreamNonBlocking);
        cudaEventCreateWithFlags(&ev_fork, cudaEventDisableTiming);
        cudaEventCreateWithFlags(&ev_join, cudaEventDisableTiming);
    }

    const int TB = 256;
    const int nblk_scan = (n + 1023) / 1024;

    // fork
    cudaEventRecord(ev_fork, 0);
    cudaStreamWaitEvent(s2, ev_fork, 0);

    // s2: first 3 CSR kernels (host submissions #1-3)
    zero_deg<<<(n + TB - 1) / TB, TB, 0, s2>>>(n);
    count_kernel<<<(e + TB - 1) / TB, TB, 0, s2>>>(dst, e);
    scan_local<<<nblk_scan, 1024, 0, s2>>>(n);

    // stream 0: gemm1 (host submission #4 — ncu capture target)
    gemm128_elr<INDIM><<<(n + 127) / 128, 256>>>(feat, W1, p_h1, al1, ar1, n);

    // s2: rest of CSR + pack
    scan_part<<<1, 32, 0, s2>>>(nblk_scan, n);
    add_part<<<(n + TB - 1) / TB, TB, 0, s2>>>(n);
    scatter_kernel<<<(e + TB - 1) / TB, TB, 0, s2>>>(src, dst, e);
    pack_W2<<<(HID * C2P + TB - 1) / TB, TB, 0, s2>>>(W2);
    cudaEventRecord(ev_join, s2);

    // join, then serial: gat1 -> gemm2 -> gat2
    cudaStreamWaitEvent(0, ev_join, 0);
    gat1_kernel<<<(n * 32 + TB - 1) / TB, TB>>>(b1, n);
    gemm_tiled_elr<HID, C2P, C2><<<(n + 63) / 64, 256>>>(p_out1, p_W2p, p_h2, al2, ar2, n, C2);
    gat2_kernel<<<(n * 32 + TB - 1) / TB, TB>>>(out, b2, n);
}

// round 11
// speedup vs baseline: 1.5303x; 1.3614x over previous
#include <cuda_runtime.h>

// Problem constants (fixed by the dataset)
#define INDIM 256
#define HID   128     // H * F1
#define NH    4
#define FD    32
#define C2    40      // classes
#define C2P   64      // padded cols for gemm2 weights
#define NMAXN 100000
#define EMAXE 1600000

typedef unsigned long long ull;

// -------- scratch (static device globals; no allocations anywhere) --------
__device__ float g_h1  [(size_t)NMAXN * HID];
__device__ float g_out1[(size_t)NMAXN * HID];
__device__ float g_h2  [(size_t)NMAXN * C2];
__device__ float g_el1 [NMAXN * NH];
__device__ float g_er1 [NMAXN * NH];
__device__ float g_el2 [NMAXN];
__device__ float g_er2 [NMAXN];
__device__ float g_e1  [(size_t)EMAXE * NH];    // slow-path scratch only
__device__ float g_e2  [EMAXE];                 // slow-path scratch only
__device__ float g_W2p [HID * C2P];
// CSR by dst
__device__ int   g_deg [NMAXN];
__device__ int   g_off [NMAXN + 1];
__device__ int   g_cur [NMAXN];
__device__ int   g_part[256];
__device__ int   g_csr_src[EMAXE];

// -------- helpers --------
__device__ __forceinline__ float lrelu(float v) { return v > 0.f ? v : 0.2f * v; }
__device__ __forceinline__ float elu(float v)   { return v > 0.f ? v : (__expf(v) - 1.f); }

__device__ __forceinline__ unsigned int f2tf32(float f) {
    unsigned int u; asm("cvt.rna.tf32.f32 %0, %1;" : "=r"(u) : "f"(f)); return u;
}

#define MMA_TF32(d, a, b) \
    asm volatile("mma.sync.aligned.m16n8k8.row.col.f32.tf32.tf32.f32 " \
        "{%0,%1,%2,%3}, {%4,%5,%6,%7}, {%8,%9}, {%0,%1,%2,%3};" \
        : "+f"((d)[0]), "+f"((d)[1]), "+f"((d)[2]), "+f"((d)[3]) \
        : "r"((a)[0]), "r"((a)[1]), "r"((a)[2]), "r"((a)[3]), \
          "r"((b)[0]), "r"((b)[1]))

// packed fp32x2 FMA (kept for gemm2)
__device__ __forceinline__ void fma2(ull& d, ull a, ull b) {
    asm("fma.rn.f32x2 %0, %1, %2, %0;" : "+l"(d) : "l"(a), "l"(b));
}
__device__ __forceinline__ ull dupf(float x) {
    ull r; asm("mov.b64 %0, {%1, %1};" : "=l"(r) : "f"(x)); return r;
}
__device__ __forceinline__ void unpk(ull p, float& lo, float& hi) {
    asm("mov.b64 {%0, %1}, %2;" : "=f"(lo), "=f"(hi) : "l"(p));
}

// ============================================================================
// GEMM1 (TF32 tensor cores) + fused elr1.
// Block 128x128, K=256, BK=32. 8 warps in 4x2; warp = 32x64 = 2x8 m16n8k8.
// Smem pads chosen for conflict-free fragment loads (As%32==4, Ws%32==8).
// ============================================================================
__global__ __launch_bounds__(256)
void gemm1_tc(const float* __restrict__ A, const float* __restrict__ W,
              float* __restrict__ C,
              const float* __restrict__ al, const float* __restrict__ ar,
              int nrows)
{
    __shared__ unsigned int As[128][36];   // [row][k]
    __shared__ unsigned int Ws[32][136];   // [k][col]
    __shared__ float sel[128][4], ser[128][4];

    const int tid  = threadIdx.x;
    const int wid  = tid >> 5;
    const int lane = tid & 31;
    const int wr   = wid >> 1;    // 0..3 : 32-row band
    const int wc   = wid & 1;     // 0..1 : 64-col band
    const int r0   = blockIdx.x * 128;
    const int qr   = lane >> 2;   // 0..7
    const int qc   = lane & 3;    // 0..3

    float acc[2][8][4];
#pragma unroll
    for (int mt = 0; mt < 2; mt++)
#pragma unroll
        for (int nt = 0; nt < 8; nt++)
#pragma unroll
            for (int j = 0; j < 4; j++) acc[mt][nt][j] = 0.f;

    for (int kt = 0; kt < INDIM; kt += 32) {
        // A tile: 128x32 floats -> tf32 bits
#pragma unroll
        for (int i = 0; i < 4; i++) {
            int idx = tid + i * 256;
            int row = idx >> 3;
            int q   = (idx & 7) * 4;
            float4 v = make_float4(0.f, 0.f, 0.f, 0.f);
            if (r0 + row < nrows)
                v = *(const float4*)(A + (size_t)(r0 + row) * INDIM + kt + q);
            As[row][q + 0] = f2tf32(v.x); As[row][q + 1] = f2tf32(v.y);
            As[row][q + 2] = f2tf32(v.z); As[row][q + 3] = f2tf32(v.w);
        }
        // W tile: 32x128
#pragma unroll
        for (int i = 0; i < 4; i++) {
            int idx = tid + i * 256;
            int kr  = idx >> 5;
            int cq  = (idx & 31) * 4;
            float4 v = *(const float4*)(W + (size_t)(kt + kr) * 128 + cq);
            Ws[kr][cq + 0] = f2tf32(v.x); Ws[kr][cq + 1] = f2tf32(v.y);
            Ws[kr][cq + 2] = f2tf32(v.z); Ws[kr][cq + 3] = f2tf32(v.w);
        }
        __syncthreads();

#pragma unroll
        for (int kc = 0; kc < 4; kc++) {
            const int k0 = kc * 8;
            unsigned int a[2][4], b[8][2];
#pragma unroll
            for (int mt = 0; mt < 2; mt++) {
                int row = wr * 32 + mt * 16 + qr;
                a[mt][0] = As[row    ][k0 + qc];
                a[mt][1] = As[row + 8][k0 + qc];
                a[mt][2] = As[row    ][k0 + qc + 4];
                a[mt][3] = As[row + 8][k0 + qc + 4];
            }
#pragma unroll
            for (int nt = 0; nt < 8; nt++) {
                int col = wc * 64 + nt * 8 + qr;
                b[nt][0] = Ws[k0 + qc    ][col];
                b[nt][1] = Ws[k0 + qc + 4][col];
            }
#pragma unroll
            for (int mt = 0; mt < 2; mt++)
#pragma unroll
                for (int nt = 0; nt < 8; nt++)
                    MMA_TF32(acc[mt][nt], a[mt], b[nt]);
        }
        __syncthreads();
    }

    // zero elr accumulators
    if (tid < 128) {
        *(float4*)(&sel[tid][0]) = make_float4(0.f, 0.f, 0.f, 0.f);
        *(float4*)(&ser[tid][0]) = make_float4(0.f, 0.f, 0.f, 0.f);
    }
    __syncthreads();

    // epilogue: store C + accumulate per-head el/er into shared
#pragma unroll
    for (int mt = 0; mt < 2; mt++) {
#pragma unroll
        for (int half = 0; half < 2; half++) {
            int lrow = wr * 32 + mt * 16 + qr + half * 8;
            int grow = r0 + lrow;
            bool ok = grow < nrows;
            float pel[2] = {0.f, 0.f}, per[2] = {0.f, 0.f};
#pragma unroll
            for (int nt = 0; nt < 8; nt++) {
                float v0 = acc[mt][nt][half * 2 + 0];
                float v1 = acc[mt][nt][half * 2 + 1];
                int col0 = wc * 64 + nt * 8 + qc * 2;
                if (ok)
                    *(float2*)(C + (size_t)grow * 128 + col0) = make_float2(v0, v1);
                int h = nt >> 2;
                pel[h] += v0 * al[col0] + v1 * al[col0 + 1];
                per[h] += v0 * ar[col0] + v1 * ar[col0 + 1];
            }
            atomicAdd(&sel[lrow][2 * wc + 0], pel[0]);
            atomicAdd(&sel[lrow][2 * wc + 1], pel[1]);
            atomicAdd(&ser[lrow][2 * wc + 0], per[0]);
            atomicAdd(&ser[lrow][2 * wc + 1], per[1]);
        }
    }
    __syncthreads();

    if (tid < 128 && r0 + tid < nrows) {
        *(float4*)(g_el1 + (size_t)(r0 + tid) * 4) = *(float4*)(&sel[tid][0]);
        *(float4*)(g_er1 + (size_t)(r0 + tid) * 4) = *(float4*)(&ser[tid][0]);
    }
}

// ============================================================================
// GEMM2 + fused elr2 (fp32, f32x2 accumulators) — unchanged from R10
// ============================================================================
template <int K, int NC, int NCREAL>
__global__ __launch_bounds__(256)
void gemm_tiled_elr(const float* __restrict__ A, const float* __restrict__ W,
                    float* __restrict__ C,
                    const float* __restrict__ al, const float* __restrict__ ar,
                    int nrows, int ostride)
{
    __shared__ float fsh[64][32];
    __shared__ float wsh[32][NC];

    const int tid = threadIdx.x;
    const int r0  = blockIdx.x * 64;
    const int cx  = tid & 31;
    const int ry  = tid >> 5;

    ull acc2[8];
#pragma unroll
    for (int i = 0; i < 8; i++) acc2[i] = 0ULL;

    for (int kt = 0; kt < K; kt += 32) {
#pragma unroll
        for (int i = 0; i < 2; i++) {
            int idx = tid + i * 256;
            int r = idx >> 3, kq = idx & 7;
            int row = r0 + r;
            float4 v = make_float4(0.f, 0.f, 0.f, 0.f);
            if (row < nrows)
                v = *(const float4*)(A + (size_t)row * K + kt + kq * 4);
            *(float4*)(&fsh[r][kq * 4]) = v;
        }
#pragma unroll
        for (int i = 0; i < 2; i++) {
            int idx = tid + i * 256;
            int kr = idx / (NC / 4), cq = idx % (NC / 4);
            *(float4*)(&wsh[kr][cq * 4]) =
                *(const float4*)(W + (size_t)(kt + kr) * NC + cq * 4);
        }
        __syncthreads();

#pragma unroll
        for (int k = 0; k < 32; k++) {
            ull wp = *(const ull*)(&wsh[k][cx * 2]);
#pragma unroll
            for (int i = 0; i < 8; i++) {
                ull fd = dupf(fsh[ry * 8 + i][k]);
                fma2(acc2[i], fd, wp);
            }
        }
        __syncthreads();
    }

    float acc[8][2];
#pragma unroll
    for (int i = 0; i < 8; i++) unpk(acc2[i], acc[i][0], acc[i][1]);

    int c0 = cx * 2, c1 = cx * 2 + 1;
    float al0 = (c0 < NCREAL) ? al[c0] : 0.f;
    float al1v = (c1 < NCREAL) ? al[c1] : 0.f;
    float ar0 = (c0 < NCREAL) ? ar[c0] : 0.f;
    float ar1v = (c1 < NCREAL) ? ar[c1] : 0.f;

#pragma unroll
    for (int i = 0; i < 8; i++) {
        int row = r0 + ry * 8 + i;
        bool ok = row < nrows;
        if (ok) {
            if (c0 < NCREAL) C[(size_t)row * ostride + c0] = acc[i][0];
            if (c1 < NCREAL) C[(size_t)row * ostride + c1] = acc[i][1];
        }
        float pel = acc[i][0] * al0 + acc[i][1] * al1v;
        float per = acc[i][0] * ar0 + acc[i][1] * ar1v;
#pragma unroll
        for (int o = 16; o; o >>= 1) {
            pel += __shfl_xor_sync(0xffffffffu, pel, o);
            per += __shfl_xor_sync(0xffffffffu, per, o);
        }
        if (cx == 0 && ok) {
            g_el2[row] = pel;
            g_er2[row] = per;
        }
    }
}

// ============================================================================
// CSR build
// ============================================================================
__global__ void zero_deg(int n)
{
    int i = blockIdx.x * blockDim.x + threadIdx.x;
    if (i < n) g_deg[i] = 0;
}

__global__ void count_kernel(const int* __restrict__ dst, int e)
{
    int i = blockIdx.x * blockDim.x + threadIdx.x;
    if (i < e) atomicAdd(&g_deg[dst[i]], 1);
}

__global__ __launch_bounds__(1024)
void scan_local(int n)
{
    __shared__ int sh[1024];
    int t = threadIdx.x;
    int i = blockIdx.x * 1024 + t;
    int val = (i < n) ? g_deg[i] : 0;
    sh[t] = val;
    __syncthreads();
#pragma unroll
    for (int d = 1; d < 1024; d <<= 1) {
        int x = (t >= d) ? sh[t - d] : 0;
        __syncthreads();
        sh[t] += x;
        __syncthreads();
    }
    if (i < n) g_off[i] = sh[t] - val;
    if (t == 1023) g_part[blockIdx.x] = sh[1023];
}

__global__ void scan_part(int nblk, int n)
{
    if (threadIdx.x != 0 || blockIdx.x != 0) return;
    int run = 0;
    for (int b = 0; b < nblk; b++) {
        int v = g_part[b];
        g_part[b] = run;
        run += v;
    }
    g_off[n] = run;
}

__global__ void add_part(int n)
{
    int i = blockIdx.x * blockDim.x + threadIdx.x;
    if (i >= n) return;
    int o = g_off[i] + g_part[i >> 10];
    g_off[i] = o;
    g_cur[i] = o;
}

__global__ void scatter_kernel(const int* __restrict__ src, const int* __restrict__ dst, int e)
{
    int i = blockIdx.x * blockDim.x + threadIdx.x;
    if (i >= e) return;
    int d = dst[i];
    int pos = atomicAdd(&g_cur[d], 1);
    g_csr_src[pos] = src[i];
}

__global__ void pack_W2(const float* __restrict__ W2)
{
    int i = blockIdx.x * blockDim.x + threadIdx.x;
    if (i >= HID * C2P) return;
    int k = i / C2P, c = i % C2P;
    g_W2p[i] = (c < C2) ? W2[k * C2 + c] : 0.f;
}

// ============================================================================
// Layer 1: warp per node — register softmax (no max pass), simple gather
// ============================================================================
__global__ __launch_bounds__(256)
void gat1_kernel(const float* __restrict__ b1, int n)
{
    __shared__ float s_alpha[8][32][4];
    __shared__ int   s_src[8][32];

    int w    = threadIdx.x >> 5;
    int node = (blockIdx.x * blockDim.x + threadIdx.x) >> 5;
    int lane = threadIdx.x & 31;
    if (node >= n) return;

    int off = g_off[node];
    int deg = g_off[node + 1] - off;
    int head = lane >> 3;

    float4 erd = *(const float4*)(g_er1 + (size_t)node * 4);
    float4 acc = make_float4(0.f, 0.f, 0.f, 0.f);

    if (deg <= 32) {
        bool valid = lane < deg;
        int s = 0;
        float4 ee = make_float4(0.f, 0.f, 0.f, 0.f);
        if (valid) {
            s = g_csr_src[off + lane];
            float4 a = *(const float4*)(g_el1 + (size_t)s * 4);
            ee.x = __expf(lrelu(a.x + erd.x));
            ee.y = __expf(lrelu(a.y + erd.y));
            ee.z = __expf(lrelu(a.z + erd.z));
            ee.w = __expf(lrelu(a.w + erd.w));
        }
        float4 sm = ee;
#pragma unroll
        for (int o = 16; o; o >>= 1) {
            sm.x += __shfl_xor_sync(0xffffffffu, sm.x, o);
            sm.y += __shfl_xor_sync(0xffffffffu, sm.y, o);
            sm.z += __shfl_xor_sync(0xffffffffu, sm.z, o);
            sm.w += __shfl_xor_sync(0xffffffffu, sm.w, o);
        }
        float4 al4 = make_float4(0.f, 0.f, 0.f, 0.f);
        if (valid) {
            al4.x = ee.x / sm.x; al4.y = ee.y / sm.y;
            al4.z = ee.z / sm.z; al4.w = ee.w / sm.w;
        }
        s_src[w][lane] = s;
        *(float4*)(&s_alpha[w][lane][0]) = al4;
        __syncwarp();

        for (int q = 0; q < deg; q++) {
            int   sq = s_src[w][q];
            float a  = s_alpha[w][q][head];
            float4 hv = *(const float4*)(g_h1 + (size_t)sq * HID + lane * 4);
            acc.x += a * hv.x; acc.y += a * hv.y;
            acc.z += a * hv.z; acc.w += a * hv.w;
        }
    } else {
        float4 sm = make_float4(0.f, 0.f, 0.f, 0.f);
        for (int base = 0; base < deg; base += 32) {
            int j = base + lane;
            if (j < deg) {
                int s = g_csr_src[off + j];
                float4 a = *(const float4*)(g_el1 + (size_t)s * 4);
                float4 e4;
                e4.x = __expf(lrelu(a.x + erd.x));
                e4.y = __expf(lrelu(a.y + erd.y));
                e4.z = __expf(lrelu(a.z + erd.z));
                e4.w = __expf(lrelu(a.w + erd.w));
                *(float4*)(g_e1 + (size_t)(off + j) * 4) = e4;
                sm.x += e4.x; sm.y += e4.y; sm.z += e4.z; sm.w += e4.w;
            }
        }
#pragma unroll
        for (int o = 16; o; o >>= 1) {
            sm.x += __shfl_xor_sync(0xffffffffu, sm.x, o);
            sm.y += __shfl_xor_sync(0xffffffffu, sm.y, o);
            sm.z += __shfl_xor_sync(0xffffffffu, sm.z, o);
            sm.w += __shfl_xor_sync(0xffffffffu, sm.w, o);
        }
        float invh = 1.f / ((head == 0) ? sm.x : (head == 1) ? sm.y : (head == 2) ? sm.z : sm.w);

        for (int base = 0; base < deg; base += 32) {
            int cnt = min(32, deg - base);
            int j = base + lane;
            int s = 0;
            float4 ee = make_float4(0.f, 0.f, 0.f, 0.f);
            if (j < deg) {
                s = g_csr_src[off + j];
                ee = *(const float4*)(g_e1 + (size_t)(off + j) * 4);
            }
            s_src[w][lane] = s;
            *(float4*)(&s_alpha[w][lane][0]) = ee;
            __syncwarp();
            for (int q = 0; q < cnt; q++) {
                int   sq = s_src[w][q];
                float a  = s_alpha[w][q][head] * invh;
                float4 hv = *(const float4*)(g_h1 + (size_t)sq * HID + lane * 4);
                acc.x += a * hv.x; acc.y += a * hv.y;
                acc.z += a * hv.z; acc.w += a * hv.w;
            }
            __syncwarp();
        }
    }

    float4 bb = *(const float4*)(b1 + lane * 4);
    float4 o;
    o.x = elu(acc.x + bb.x); o.y = elu(acc.y + bb.y);
    o.z = elu(acc.z + bb.z); o.w = elu(acc.w + bb.w);
    *(float4*)(g_out1 + (size_t)node * HID + lane * 4) = o;
}

// ============================================================================
// Layer 2: warp per node (1 head, C=40); no max pass; simple gather
// ============================================================================
__global__ __launch_bounds__(256)
void gat2_kernel(float* __restrict__ out, const float* __restrict__ b2, int n)
{
    __shared__ float s_a[8][32];
    __shared__ int   s_src[8][32];

    int w    = threadIdx.x >> 5;
    int node = (blockIdx.x * blockDim.x + threadIdx.x) >> 5;
    int lane = threadIdx.x & 31;
    if (node >= n) return;

    int off = g_off[node];
    int deg = g_off[node + 1] - off;
    float erd = g_er2[node];

    float acc0 = 0.f, acc1 = 0.f;

    if (deg <= 32) {
        bool valid = lane < deg;
        int s = 0;
        float ee = 0.f;
        if (valid) {
            s = g_csr_src[off + lane];
            ee = __expf(lrelu(g_el2[s] + erd));
        }
        float sm = ee;
#pragma unroll
        for (int o = 16; o; o >>= 1)
            sm += __shfl_xor_sync(0xffffffffu, sm, o);
        float alpha = valid ? (ee / sm) : 0.f;

        s_src[w][lane] = s;
        s_a[w][lane] = alpha;
        __syncwarp();

        for (int q = 0; q < deg; q++) {
            int   sq = s_src[w][q];
            float a  = s_a[w][q];
            const float* hp = g_h2 + (size_t)sq * C2;
            acc0 += a * hp[lane];
            if (lane < 8) acc1 += a * hp[32 + lane];
        }
    } else {
        float sm = 0.f;
        for (int base = 0; base < deg; base += 32) {
            int j = base + lane;
            if (j < deg) {
                int s = g_csr_src[off + j];
                float ee = __expf(lrelu(g_el2[s] + erd));
                g_e2[off + j] = ee;
                sm += ee;
            }
        }
#pragma unroll
        for (int o = 16; o; o >>= 1)
            sm += __shfl_xor_sync(0xffffffffu, sm, o);
        float inv = 1.f / sm;

        for (int base = 0; base < deg; base += 32) {
            int cnt = min(32, deg - base);
            int j = base + lane;
            int s = 0; float ee = 0.f;
            if (j < deg) {
                s = g_csr_src[off + j];
                ee = g_e2[off + j];
            }
            s_src[w][lane] = s;
            s_a[w][lane] = ee * inv;
            __syncwarp();
            for (int q = 0; q < cnt; q++) {
                int   sq = s_src[w][q];
                float a  = s_a[w][q];
                const float* hp = g_h2 + (size_t)sq * C2;
                acc0 += a * hp[lane];
                if (lane < 8) acc1 += a * hp[32 + lane];
            }
            __syncwarp();
        }
    }

    out[(size_t)node * C2 + lane] = acc0 + b2[lane];
    if (lane < 8)
        out[(size_t)node * C2 + 32 + lane] = acc1 + b2[32 + lane];
}

// ============================================================================
// launch — R9 schedule (gemm1 is host submission #4 = ncu capture target)
// ============================================================================
extern "C" void kernel_launch(void* const* d_in, const int* in_sizes, int n_in,
                              void* d_out, int out_size)
{
    const float* feat = (const float*)d_in[0];
    const int*   src  = (const int*)  d_in[1];
    const int*   dst  = (const int*)  d_in[2];
    const float* W1   = (const float*)d_in[3];
    const float* al1  = (const float*)d_in[4];
    const float* ar1  = (const float*)d_in[5];
    const float* b1   = (const float*)d_in[6];
    const float* W2   = (const float*)d_in[7];
    const float* al2  = (const float*)d_in[8];
    const float* ar2  = (const float*)d_in[9];
    const float* b2   = (const float*)d_in[10];
    float* out = (float*)d_out;

    const int n = in_sizes[0] / INDIM;   // 100000
    const int e = in_sizes[1];           // 1600000

    float *p_h1 = 0, *p_out1 = 0, *p_h2 = 0, *p_W2p = 0;
    cudaGetSymbolAddress((void**)&p_h1,   g_h1);
    cudaGetSymbolAddress((void**)&p_out1, g_out1);
    cudaGetSymbolAddress((void**)&p_h2,   g_h2);
    cudaGetSymbolAddress((void**)&p_W2p,  g_W2p);

    static cudaStream_t s2 = 0;
    static cudaEvent_t ev_fork = 0, ev_join = 0;
    if (!s2) {
        cudaStreamCreateWithFlags(&s2, cudaStreamNonBlocking);
        cudaEventCreateWithFlags(&ev_fork, cudaEventDisableTiming);
        cudaEventCreateWithFlags(&ev_join, cudaEventDisableTiming);
    }

    const int TB = 256;
    const int nblk_scan = (n + 1023) / 1024;

    // fork
    cudaEventRecord(ev_fork, 0);
    cudaStreamWaitEvent(s2, ev_fork, 0);

    // s2: first 3 CSR kernels (host submissions #1-3)
    zero_deg<<<(n + TB - 1) / TB, TB, 0, s2>>>(n);
    count_kernel<<<(e + TB - 1) / TB, TB, 0, s2>>>(dst, e);
    scan_local<<<nblk_scan, 1024, 0, s2>>>(n);

    // stream 0: gemm1 TF32 tensor-core (host submission #4 — ncu target)
    gemm1_tc<<<(n + 127) / 128, 256>>>(feat, W1, p_h1, al1, ar1, n);

    // s2: rest of CSR + pack
    scan_part<<<1, 32, 0, s2>>>(nblk_scan, n);
    add_part<<<(n + TB - 1) / TB, TB, 0, s2>>>(n);
    scatter_kernel<<<(e + TB - 1) / TB, TB, 0, s2>>>(src, dst, e);
    pack_W2<<<(HID * C2P + TB - 1) / TB, TB, 0, s2>>>(W2);
    cudaEventRecord(ev_join, s2);

    // join, then serial: gat1 -> gemm2 -> gat2
    cudaStreamWaitEvent(0, ev_join, 0);
    gat1_kernel<<<(n * 32 + TB - 1) / TB, TB>>>(b1, n);
    gemm_tiled_elr<HID, C2P, C2><<<(n + 63) / 64, 256>>>(p_out1, p_W2p, p_h2, al2, ar2, n, C2);
    gat2_kernel<<<(n * 32 + TB - 1) / TB, TB>>>(out, b2, n);
}

// round 12
// speedup vs baseline: 1.6620x; 1.0861x over previous
#include <cuda_runtime.h>

// Problem constants (fixed by the dataset)
#define INDIM 256
#define HID   128     // H * F1
#define NH    4
#define FD    32
#define C2    40      // classes
#define NMAXN 100000
#define EMAXE 1600000

// -------- scratch (static device globals; no allocations anywhere) --------
__device__ float g_h1  [(size_t)NMAXN * HID];
__device__ float g_out1[(size_t)NMAXN * HID];
__device__ float g_h2  [(size_t)NMAXN * C2];
__device__ float g_el1 [NMAXN * NH];
__device__ float g_er1 [NMAXN * NH];
__device__ float g_el2 [NMAXN];
__device__ float g_er2 [NMAXN];
__device__ float g_e1  [(size_t)EMAXE * NH];    // slow-path scratch only
__device__ float g_e2  [EMAXE];                 // slow-path scratch only
// CSR by dst
__device__ int   g_deg [NMAXN];
__device__ int   g_off [NMAXN + 1];
__device__ int   g_cur [NMAXN];
__device__ int   g_part[256];
__device__ int   g_csr_src[EMAXE];

// -------- helpers --------
__device__ __forceinline__ float lrelu(float v) { return v > 0.f ? v : 0.2f * v; }
__device__ __forceinline__ float elu(float v)   { return v > 0.f ? v : (__expf(v) - 1.f); }

__device__ __forceinline__ unsigned int f2tf32(float f) {
    unsigned int u; asm("cvt.rna.tf32.f32 %0, %1;" : "=r"(u) : "f"(f)); return u;
}

#define MMA_TF32(d, a, b) \
    asm volatile("mma.sync.aligned.m16n8k8.row.col.f32.tf32.tf32.f32 " \
        "{%0,%1,%2,%3}, {%4,%5,%6,%7}, {%8,%9}, {%0,%1,%2,%3};" \
        : "+f"((d)[0]), "+f"((d)[1]), "+f"((d)[2]), "+f"((d)[3]) \
        : "r"((a)[0]), "r"((a)[1]), "r"((a)[2]), "r"((a)[3]), \
          "r"((b)[0]), "r"((b)[1]))

// ============================================================================
// GEMM1 (TF32 tensor cores) + fused elr1 — unchanged from R11 (validated).
// Block 128x128, K=256, BK=32. 8 warps 4x2; warp = 32x64 = 2x8 m16n8k8.
// ============================================================================
__global__ __launch_bounds__(256)
void gemm1_tc(const float* __restrict__ A, const float* __restrict__ W,
              float* __restrict__ C,
              const float* __restrict__ al, const float* __restrict__ ar,
              int nrows)
{
    __shared__ unsigned int As[128][36];   // [row][k]
    __shared__ unsigned int Ws[32][136];   // [k][col]
    __shared__ float sel[128][4], ser[128][4];

    const int tid  = threadIdx.x;
    const int wid  = tid >> 5;
    const int lane = tid & 31;
    const int wr   = wid >> 1;
    const int wc   = wid & 1;
    const int r0   = blockIdx.x * 128;
    const int qr   = lane >> 2;
    const int qc   = lane & 3;

    float acc[2][8][4];
#pragma unroll
    for (int mt = 0; mt < 2; mt++)
#pragma unroll
        for (int nt = 0; nt < 8; nt++)
#pragma unroll
            for (int j = 0; j < 4; j++) acc[mt][nt][j] = 0.f;

    for (int kt = 0; kt < INDIM; kt += 32) {
#pragma unroll
        for (int i = 0; i < 4; i++) {
            int idx = tid + i * 256;
            int row = idx >> 3;
            int q   = (idx & 7) * 4;
            float4 v = make_float4(0.f, 0.f, 0.f, 0.f);
            if (r0 + row < nrows)
                v = *(const float4*)(A + (size_t)(r0 + row) * INDIM + kt + q);
            As[row][q + 0] = f2tf32(v.x); As[row][q + 1] = f2tf32(v.y);
            As[row][q + 2] = f2tf32(v.z); As[row][q + 3] = f2tf32(v.w);
        }
#pragma unroll
        for (int i = 0; i < 4; i++) {
            int idx = tid + i * 256;
            int kr  = idx >> 5;
            int cq  = (idx & 31) * 4;
            float4 v = *(const float4*)(W + (size_t)(kt + kr) * 128 + cq);
            Ws[kr][cq + 0] = f2tf32(v.x); Ws[kr][cq + 1] = f2tf32(v.y);
            Ws[kr][cq + 2] = f2tf32(v.z); Ws[kr][cq + 3] = f2tf32(v.w);
        }
        __syncthreads();

#pragma unroll
        for (int kc = 0; kc < 4; kc++) {
            const int k0 = kc * 8;
            unsigned int a[2][4], b[8][2];
#pragma unroll
            for (int mt = 0; mt < 2; mt++) {
                int row = wr * 32 + mt * 16 + qr;
                a[mt][0] = As[row    ][k0 + qc];
                a[mt][1] = As[row + 8][k0 + qc];
                a[mt][2] = As[row    ][k0 + qc + 4];
                a[mt][3] = As[row + 8][k0 + qc + 4];
            }
#pragma unroll
            for (int nt = 0; nt < 8; nt++) {
                int col = wc * 64 + nt * 8 + qr;
                b[nt][0] = Ws[k0 + qc    ][col];
                b[nt][1] = Ws[k0 + qc + 4][col];
            }
#pragma unroll
            for (int mt = 0; mt < 2; mt++)
#pragma unroll
                for (int nt = 0; nt < 8; nt++)
                    MMA_TF32(acc[mt][nt], a[mt], b[nt]);
        }
        __syncthreads();
    }

    if (tid < 128) {
        *(float4*)(&sel[tid][0]) = make_float4(0.f, 0.f, 0.f, 0.f);
        *(float4*)(&ser[tid][0]) = make_float4(0.f, 0.f, 0.f, 0.f);
    }
    __syncthreads();

#pragma unroll
    for (int mt = 0; mt < 2; mt++) {
#pragma unroll
        for (int half = 0; half < 2; half++) {
            int lrow = wr * 32 + mt * 16 + qr + half * 8;
            int grow = r0 + lrow;
            bool ok = grow < nrows;
            float pel[2] = {0.f, 0.f}, per[2] = {0.f, 0.f};
#pragma unroll
            for (int nt = 0; nt < 8; nt++) {
                float v0 = acc[mt][nt][half * 2 + 0];
                float v1 = acc[mt][nt][half * 2 + 1];
                int col0 = wc * 64 + nt * 8 + qc * 2;
                if (ok)
                    *(float2*)(C + (size_t)grow * 128 + col0) = make_float2(v0, v1);
                int h = nt >> 2;
                pel[h] += v0 * al[col0] + v1 * al[col0 + 1];
                per[h] += v0 * ar[col0] + v1 * ar[col0 + 1];
            }
            atomicAdd(&sel[lrow][2 * wc + 0], pel[0]);
            atomicAdd(&sel[lrow][2 * wc + 1], pel[1]);
            atomicAdd(&ser[lrow][2 * wc + 0], per[0]);
            atomicAdd(&ser[lrow][2 * wc + 1], per[1]);
        }
    }
    __syncthreads();

    if (tid < 128 && r0 + tid < nrows) {
        *(float4*)(g_el1 + (size_t)(r0 + tid) * 4) = *(float4*)(&sel[tid][0]);
        *(float4*)(g_er1 + (size_t)(r0 + tid) * 4) = *(float4*)(&ser[tid][0]);
    }
}

// ============================================================================
// GEMM2 (TF32 tensor cores) + fused elr2.
// Block 128 rows x 64 cols (real 40), K=128, BK=32. 8 warps 4x2;
// warp = 32x32 = 2x4 m16n8k8. Reads W2 directly (zero-pads 40->64 in smem).
// ============================================================================
__global__ __launch_bounds__(256)
void gemm2_tc(const float* __restrict__ A, const float* __restrict__ W2,
              float* __restrict__ C,
              const float* __restrict__ al, const float* __restrict__ ar,
              int nrows)
{
    __shared__ unsigned int As[128][36];   // [row][k]
    __shared__ unsigned int Ws[32][72];    // [k][col], 64 cols padded to 72
    __shared__ float sel[128], ser[128];

    const int tid  = threadIdx.x;
    const int wid  = tid >> 5;
    const int lane = tid & 31;
    const int wr   = wid >> 1;    // 0..3
    const int wc   = wid & 1;     // 0..1
    const int r0   = blockIdx.x * 128;
    const int qr   = lane >> 2;
    const int qc   = lane & 3;

    float acc[2][4][4];
#pragma unroll
    for (int mt = 0; mt < 2; mt++)
#pragma unroll
        for (int nt = 0; nt < 4; nt++)
#pragma unroll
            for (int j = 0; j < 4; j++) acc[mt][nt][j] = 0.f;

    for (int kt = 0; kt < HID; kt += 32) {
        // A tile: 128x32 (stride HID)
#pragma unroll
        for (int i = 0; i < 4; i++) {
            int idx = tid + i * 256;
            int row = idx >> 3;
            int q   = (idx & 7) * 4;
            float4 v = make_float4(0.f, 0.f, 0.f, 0.f);
            if (r0 + row < nrows)
                v = *(const float4*)(A + (size_t)(r0 + row) * HID + kt + q);
            As[row][q + 0] = f2tf32(v.x); As[row][q + 1] = f2tf32(v.y);
            As[row][q + 2] = f2tf32(v.z); As[row][q + 3] = f2tf32(v.w);
        }
        // W tile: 32x64 from W2 (32x40, zero-pad)
#pragma unroll
        for (int i = 0; i < 2; i++) {
            int idx = tid + i * 256;
            int kr  = idx >> 4;           // 0..31
            int cq  = (idx & 15) * 4;     // 0..60
            float4 v = make_float4(0.f, 0.f, 0.f, 0.f);
            if (cq < C2)                  // cq<=36 -> cq+3<=39 in range
                v = *(const float4*)(W2 + (size_t)(kt + kr) * C2 + cq);
            Ws[kr][cq + 0] = f2tf32(v.x); Ws[kr][cq + 1] = f2tf32(v.y);
            Ws[kr][cq + 2] = f2tf32(v.z); Ws[kr][cq + 3] = f2tf32(v.w);
        }
        __syncthreads();

#pragma unroll
        for (int kc = 0; kc < 4; kc++) {
            const int k0 = kc * 8;
            unsigned int a[2][4], b[4][2];
#pragma unroll
            for (int mt = 0; mt < 2; mt++) {
                int row = wr * 32 + mt * 16 + qr;
                a[mt][0] = As[row    ][k0 + qc];
                a[mt][1] = As[row + 8][k0 + qc];
                a[mt][2] = As[row    ][k0 + qc + 4];
                a[mt][3] = As[row + 8][k0 + qc + 4];
            }
#pragma unroll
            for (int nt = 0; nt < 4; nt++) {
                int col = wc * 32 + nt * 8 + qr;
                b[nt][0] = Ws[k0 + qc    ][col];
                b[nt][1] = Ws[k0 + qc + 4][col];
            }
#pragma unroll
            for (int mt = 0; mt < 2; mt++)
#pragma unroll
                for (int nt = 0; nt < 4; nt++)
                    MMA_TF32(acc[mt][nt], a[mt], b[nt]);
        }
        __syncthreads();
    }

    if (tid < 128) { sel[tid] = 0.f; ser[tid] = 0.f; }
    __syncthreads();

#pragma unroll
    for (int mt = 0; mt < 2; mt++) {
#pragma unroll
        for (int half = 0; half < 2; half++) {
            int lrow = wr * 32 + mt * 16 + qr + half * 8;
            int grow = r0 + lrow;
            bool ok = grow < nrows;
            float pel = 0.f, per = 0.f;
#pragma unroll
            for (int nt = 0; nt < 4; nt++) {
                float v0 = acc[mt][nt][half * 2 + 0];
                float v1 = acc[mt][nt][half * 2 + 1];
                int col0 = wc * 32 + nt * 8 + qc * 2;
                if (col0 < C2) {          // pairs stay in-range (C2 even)
                    if (ok)
                        *(float2*)(C + (size_t)grow * C2 + col0) = make_float2(v0, v1);
                    pel += v0 * al[col0] + v1 * al[col0 + 1];
                    per += v0 * ar[col0] + v1 * ar[col0 + 1];
                }
            }
            atomicAdd(&sel[lrow], pel);
            atomicAdd(&ser[lrow], per);
        }
    }
    __syncthreads();

    if (tid < 128 && r0 + tid < nrows) {
        g_el2[r0 + tid] = sel[tid];
        g_er2[r0 + tid] = ser[tid];
    }
}

// ============================================================================
// CSR build
// ============================================================================
__global__ void zero_deg(int n)
{
    int i = blockIdx.x * blockDim.x + threadIdx.x;
    if (i < n) g_deg[i] = 0;
}

__global__ void count_kernel(const int* __restrict__ dst, int e)
{
    int i = blockIdx.x * blockDim.x + threadIdx.x;
    if (i < e) atomicAdd(&g_deg[dst[i]], 1);
}

__global__ __launch_bounds__(1024)
void scan_local(int n)
{
    __shared__ int sh[1024];
    int t = threadIdx.x;
    int i = blockIdx.x * 1024 + t;
    int val = (i < n) ? g_deg[i] : 0;
    sh[t] = val;
    __syncthreads();
#pragma unroll
    for (int d = 1; d < 1024; d <<= 1) {
        int x = (t >= d) ? sh[t - d] : 0;
        __syncthreads();
        sh[t] += x;
        __syncthreads();
    }
    if (i < n) g_off[i] = sh[t] - val;
    if (t == 1023) g_part[blockIdx.x] = sh[1023];
}

__global__ void scan_part(int nblk, int n)
{
    if (threadIdx.x != 0 || blockIdx.x != 0) return;
    int run = 0;
    for (int b = 0; b < nblk; b++) {
        int v = g_part[b];
        g_part[b] = run;
        run += v;
    }
    g_off[n] = run;
}

__global__ void add_part(int n)
{
    int i = blockIdx.x * blockDim.x + threadIdx.x;
    if (i >= n) return;
    int o = g_off[i] + g_part[i >> 10];
    g_off[i] = o;
    g_cur[i] = o;
}

__global__ void scatter_kernel(const int* __restrict__ src, const int* __restrict__ dst, int e)
{
    int i = blockIdx.x * blockDim.x + threadIdx.x;
    if (i >= e) return;
    int d = dst[i];
    int pos = atomicAdd(&g_cur[d], 1);
    g_csr_src[pos] = src[i];
}

// ============================================================================
// Layer 1: warp per node — register softmax (no max pass), simple gather
// ============================================================================
__global__ __launch_bounds__(256)
void gat1_kernel(const float* __restrict__ b1, int n)
{
    __shared__ float s_alpha[8][32][4];
    __shared__ int   s_src[8][32];

    int w    = threadIdx.x >> 5;
    int node = (blockIdx.x * blockDim.x + threadIdx.x) >> 5;
    int lane = threadIdx.x & 31;
    if (node >= n) return;

    int off = g_off[node];
    int deg = g_off[node + 1] - off;
    int head = lane >> 3;

    float4 erd = *(const float4*)(g_er1 + (size_t)node * 4);
    float4 acc = make_float4(0.f, 0.f, 0.f, 0.f);

    if (deg <= 32) {
        bool valid = lane < deg;
        int s = 0;
        float4 ee = make_float4(0.f, 0.f, 0.f, 0.f);
        if (valid) {
            s = g_csr_src[off + lane];
            float4 a = *(const float4*)(g_el1 + (size_t)s * 4);
            ee.x = __expf(lrelu(a.x + erd.x));
            ee.y = __expf(lrelu(a.y + erd.y));
            ee.z = __expf(lrelu(a.z + erd.z));
            ee.w = __expf(lrelu(a.w + erd.w));
        }
        float4 sm = ee;
#pragma unroll
        for (int o = 16; o; o >>= 1) {
            sm.x += __shfl_xor_sync(0xffffffffu, sm.x, o);
            sm.y += __shfl_xor_sync(0xffffffffu, sm.y, o);
            sm.z += __shfl_xor_sync(0xffffffffu, sm.z, o);
            sm.w += __shfl_xor_sync(0xffffffffu, sm.w, o);
        }
        float4 al4 = make_float4(0.f, 0.f, 0.f, 0.f);
        if (valid) {
            al4.x = ee.x / sm.x; al4.y = ee.y / sm.y;
            al4.z = ee.z / sm.z; al4.w = ee.w / sm.w;
        }
        s_src[w][lane] = s;
        *(float4*)(&s_alpha[w][lane][0]) = al4;
        __syncwarp();

        for (int q = 0; q < deg; q++) {
            int   sq = s_src[w][q];
            float a  = s_alpha[w][q][head];
            float4 hv = *(const float4*)(g_h1 + (size_t)sq * HID + lane * 4);
            acc.x += a * hv.x; acc.y += a * hv.y;
            acc.z += a * hv.z; acc.w += a * hv.w;
        }
    } else {
        float4 sm = make_float4(0.f, 0.f, 0.f, 0.f);
        for (int base = 0; base < deg; base += 32) {
            int j = base + lane;
            if (j < deg) {
                int s = g_csr_src[off + j];
                float4 a = *(const float4*)(g_el1 + (size_t)s * 4);
                float4 e4;
                e4.x = __expf(lrelu(a.x + erd.x));
                e4.y = __expf(lrelu(a.y + erd.y));
                e4.z = __expf(lrelu(a.z + erd.z));
                e4.w = __expf(lrelu(a.w + erd.w));
                *(float4*)(g_e1 + (size_t)(off + j) * 4) = e4;
                sm.x += e4.x; sm.y += e4.y; sm.z += e4.z; sm.w += e4.w;
            }
        }
#pragma unroll
        for (int o = 16; o; o >>= 1) {
            sm.x += __shfl_xor_sync(0xffffffffu, sm.x, o);
            sm.y += __shfl_xor_sync(0xffffffffu, sm.y, o);
            sm.z += __shfl_xor_sync(0xffffffffu, sm.z, o);
            sm.w += __shfl_xor_sync(0xffffffffu, sm.w, o);
        }
        float invh = 1.f / ((head == 0) ? sm.x : (head == 1) ? sm.y : (head == 2) ? sm.z : sm.w);

        for (int base = 0; base < deg; base += 32) {
            int cnt = min(32, deg - base);
            int j = base + lane;
            int s = 0;
            float4 ee = make_float4(0.f, 0.f, 0.f, 0.f);
            if (j < deg) {
                s = g_csr_src[off + j];
                ee = *(const float4*)(g_e1 + (size_t)(off + j) * 4);
            }
            s_src[w][lane] = s;
            *(float4*)(&s_alpha[w][lane][0]) = ee;
            __syncwarp();
            for (int q = 0; q < cnt; q++) {
                int   sq = s_src[w][q];
                float a  = s_alpha[w][q][head] * invh;
                float4 hv = *(const float4*)(g_h1 + (size_t)sq * HID + lane * 4);
                acc.x += a * hv.x; acc.y += a * hv.y;
                acc.z += a * hv.z; acc.w += a * hv.w;
            }
            __syncwarp();
        }
    }

    float4 bb = *(const float4*)(b1 + lane * 4);
    float4 o;
    o.x = elu(acc.x + bb.x); o.y = elu(acc.y + bb.y);
    o.z = elu(acc.z + bb.z); o.w = elu(acc.w + bb.w);
    *(float4*)(g_out1 + (size_t)node * HID + lane * 4) = o;
}

// ============================================================================
// Layer 2: warp per node (1 head, C=40); no max pass; simple gather
// ============================================================================
__global__ __launch_bounds__(256)
void gat2_kernel(float* __restrict__ out, const float* __restrict__ b2, int n)
{
    __shared__ float s_a[8][32];
    __shared__ int   s_src[8][32];

    int w    = threadIdx.x >> 5;
    int node = (blockIdx.x * blockDim.x + threadIdx.x) >> 5;
    int lane = threadIdx.x & 31;
    if (node >= n) return;

    int off = g_off[node];
    int deg = g_off[node + 1] - off;
    float erd = g_er2[node];

    float acc0 = 0.f, acc1 = 0.f;

    if (deg <= 32) {
        bool valid = lane < deg;
        int s = 0;
        float ee = 0.f;
        if (valid) {
            s = g_csr_src[off + lane];
            ee = __expf(lrelu(g_el2[s] + erd));
        }
        float sm = ee;
#pragma unroll
        for (int o = 16; o; o >>= 1)
            sm += __shfl_xor_sync(0xffffffffu, sm, o);
        float alpha = valid ? (ee / sm) : 0.f;

        s_src[w][lane] = s;
        s_a[w][lane] = alpha;
        __syncwarp();

        for (int q = 0; q < deg; q++) {
            int   sq = s_src[w][q];
            float a  = s_a[w][q];
            const float* hp = g_h2 + (size_t)sq * C2;
            acc0 += a * hp[lane];
            if (lane < 8) acc1 += a * hp[32 + lane];
        }
    } else {
        float sm = 0.f;
        for (int base = 0; base < deg; base += 32) {
            int j = base + lane;
            if (j < deg) {
                int s = g_csr_src[off + j];
                float ee = __expf(lrelu(g_el2[s] + erd));
                g_e2[off + j] = ee;
                sm += ee;
            }
        }
#pragma unroll
        for (int o = 16; o; o >>= 1)
            sm += __shfl_xor_sync(0xffffffffu, sm, o);
        float inv = 1.f / sm;

        for (int base = 0; base < deg; base += 32) {
            int cnt = min(32, deg - base);
            int j = base + lane;
            int s = 0; float ee = 0.f;
            if (j < deg) {
                s = g_csr_src[off + j];
                ee = g_e2[off + j];
            }
            s_src[w][lane] = s;
            s_a[w][lane] = ee * inv;
            __syncwarp();
            for (int q = 0; q < cnt; q++) {
                int   sq = s_src[w][q];
                float a  = s_a[w][q];
                const float* hp = g_h2 + (size_t)sq * C2;
                acc0 += a * hp[lane];
                if (lane < 8) acc1 += a * hp[32 + lane];
            }
            __syncwarp();
        }
    }

    out[(size_t)node * C2 + lane] = acc0 + b2[lane];
    if (lane < 8)
        out[(size_t)node * C2 + 32 + lane] = acc1 + b2[32 + lane];
}

// ============================================================================
// launch — CSR ∥ gemm1 fork (gemm1 = submission #4, ncu target), then serial
// ============================================================================
extern "C" void kernel_launch(void* const* d_in, const int* in_sizes, int n_in,
                              void* d_out, int out_size)
{
    const float* feat = (const float*)d_in[0];
    const int*   src  = (const int*)  d_in[1];
    const int*   dst  = (const int*)  d_in[2];
    const float* W1   = (const float*)d_in[3];
    const float* al1  = (const float*)d_in[4];
    const float* ar1  = (const float*)d_in[5];
    const float* b1   = (const float*)d_in[6];
    const float* W2   = (const float*)d_in[7];
    const float* al2  = (const float*)d_in[8];
    const float* ar2  = (const float*)d_in[9];
    const float* b2   = (const float*)d_in[10];
    float* out = (float*)d_out;

    const int n = in_sizes[0] / INDIM;   // 100000
    const int e = in_sizes[1];           // 1600000

    float *p_h1 = 0, *p_out1 = 0, *p_h2 = 0;
    cudaGetSymbolAddress((void**)&p_h1,   g_h1);
    cudaGetSymbolAddress((void**)&p_out1, g_out1);
    cudaGetSymbolAddress((void**)&p_h2,   g_h2);

    static cudaStream_t s2 = 0;
    static cudaEvent_t ev_fork = 0, ev_join = 0;
    if (!s2) {
        cudaStreamCreateWithFlags(&s2, cudaStreamNonBlocking);
        cudaEventCreateWithFlags(&ev_fork, cudaEventDisableTiming);
        cudaEventCreateWithFlags(&ev_join, cudaEventDisableTiming);
    }

    const int TB = 256;
    const int nblk_scan = (n + 1023) / 1024;

    // fork
    cudaEventRecord(ev_fork, 0);
    cudaStreamWaitEvent(s2, ev_fork, 0);

    // s2: first 3 CSR kernels (#1-3)
    zero_deg<<<(n + TB - 1) / TB, TB, 0, s2>>>(n);
    count_kernel<<<(e + TB - 1) / TB, TB, 0, s2>>>(dst, e);
    scan_local<<<nblk_scan, 1024, 0, s2>>>(n);

    // stream 0: gemm1 TF32 (#4 — ncu target)
    gemm1_tc<<<(n + 127) / 128, 256>>>(feat, W1, p_h1, al1, ar1, n);

    // s2: rest of CSR
    scan_part<<<1, 32, 0, s2>>>(nblk_scan, n);
    add_part<<<(n + TB - 1) / TB, TB, 0, s2>>>(n);
    scatter_kernel<<<(e + TB - 1) / TB, TB, 0, s2>>>(src, dst, e);
    cudaEventRecord(ev_join, s2);

    // join, then serial: gat1 -> gemm2 (TF32) -> gat2
    cudaStreamWaitEvent(0, ev_join, 0);
    gat1_kernel<<<(n * 32 + TB - 1) / TB, TB>>>(b1, n);
    gemm2_tc<<<(n + 127) / 128, 256>>>(p_out1, W2, p_h2, al2, ar2, n);
    gat2_kernel<<<(n * 32 + TB - 1) / TB, TB>>>(out, b2, n);
}